// round 2
// baseline (speedup 1.0000x reference)
#include <cuda_runtime.h>
#include <math.h>

// Problem constants: B=2, M=N=64, H=2, C=8, D=4
#define TOK  4096          // tokens per batch image (64*64)
#define TOT  8192          // total tokens (B*TOK)

// Scratch (allocation-free: __device__ globals)
__device__ float g_gelu[65536];    // gelu(x)
__device__ float g_x1[65536];      // after conv block + residual
__device__ float g_q[65536];       // [bh][t][d], pre-scaled by 0.5 (1/sqrt(d))
__device__ float g_k[65536];
__device__ float g_v[65536];
__device__ float g_a[65536];       // attention output [bh][t][d]
__device__ float g_x2[65536];      // after attention + residual
__device__ float g_t1[262144];     // mlp hidden 1 (32 ch)
__device__ float g_t2[262144];     // mlp hidden 2 (32 ch)

__device__ __forceinline__ float gelu_f(float x) {
    // jax.nn.gelu default (approximate=True, tanh form)
    float x3 = x * x * x;
    float t = tanhf(0.7978845608028654f * fmaf(0.044715f, x3, x));
    return 0.5f * x * (1.0f + t);
}

// ---------------- Stage 0: gelu(x) ----------------
__global__ void k_gelu(const float* __restrict__ x) {
    int i = blockIdx.x * blockDim.x + threadIdx.x;
    if (i < 65536) g_gelu[i] = gelu_f(x[i]);
}

// ---------------- Stage 1: circular 3x3 conv (8->8) + bias + residual ----------------
__global__ void k_conv1(const float* __restrict__ x, const float* __restrict__ W,
                        const float* __restrict__ bias) {
    __shared__ float sW[576];   // (3,3,8,8) HWIO
    __shared__ float sb[8];
    for (int i = threadIdx.x; i < 576; i += blockDim.x) sW[i] = W[i];
    if (threadIdx.x < 8) sb[threadIdx.x] = bias[threadIdx.x];
    __syncthreads();
    int p = blockIdx.x * blockDim.x + threadIdx.x;
    if (p >= TOT) return;
    int b = p >> 12, rem = p & 4095, i = rem >> 6, j = rem & 63;
    float acc[8];
#pragma unroll
    for (int c = 0; c < 8; c++) acc[c] = sb[c] + x[p * 8 + c];
#pragma unroll
    for (int di = 0; di < 3; di++) {
        int row = (i + di + 63) & 63;
#pragma unroll
        for (int dj = 0; dj < 3; dj++) {
            int col = (j + dj + 63) & 63;
            const float* gp = g_gelu + ((((b << 12) | (row << 6)) | col) << 3);
            const float* wp = sW + (di * 3 + dj) * 64;
#pragma unroll
            for (int cin = 0; cin < 8; cin++) {
                float xv = gp[cin];
#pragma unroll
                for (int c = 0; c < 8; c++) acc[c] = fmaf(xv, wp[cin * 8 + c], acc[c]);
            }
        }
    }
#pragma unroll
    for (int c = 0; c < 8; c++) g_x1[p * 8 + c] = acc[c];
}

// ---------------- Stage 2: QKV projections (y = x1/sqrt(2)), q pre-scaled by 0.5 ----------------
__global__ void k_qkv(const float* __restrict__ Wq, const float* __restrict__ Wk,
                      const float* __restrict__ Wv) {
    __shared__ float sW[192];   // Wq|Wk|Wv, each 8x8
    if (threadIdx.x < 64) {
        sW[threadIdx.x]       = Wq[threadIdx.x];
        sW[64 + threadIdx.x]  = Wk[threadIdx.x];
        sW[128 + threadIdx.x] = Wv[threadIdx.x];
    }
    __syncthreads();
    int p = blockIdx.x * blockDim.x + threadIdx.x;
    if (p >= TOT) return;
    int b = p >> 12, t = p & 4095;
    float y[8];
#pragma unroll
    for (int c = 0; c < 8; c++) y[c] = g_x1[p * 8 + c] * 0.70710678118654752f;
#pragma unroll
    for (int e = 0; e < 8; e++) {
        float qe = 0.f, ke = 0.f, ve = 0.f;
#pragma unroll
        for (int c = 0; c < 8; c++) {
            qe = fmaf(y[c], sW[c * 8 + e], qe);
            ke = fmaf(y[c], sW[64 + c * 8 + e], ke);
            ve = fmaf(y[c], sW[128 + c * 8 + e], ve);
        }
        int h = e >> 2, d = e & 3;
        int idx = (((b << 1) | h) * TOK + t) * 4 + d;
        g_q[idx] = qe * 0.5f;    // fold 1/sqrt(d)=0.5
        g_k[idx] = ke;
        g_v[idx] = ve;
    }
}

// ---------------- Stage 3: attention (DIAGONAL semantics: a_n = attn[n,n] * v_n) ----------------
// Only the softmax denominator (logsumexp over keys) is needed per query, plus the self-score.
// grid = (64 q-tiles, 4 bh), 256 threads (8 warps x 8 queries each), smem = K + pos = 80KB
__global__ void __launch_bounds__(256) k_attn(const float* __restrict__ pos) {
    extern __shared__ float smem[];
    float* sK = smem;              // 16384 floats (K as float4[4096])
    float* sP = smem + 16384;      // 4096 floats (pre-scaled by 0.5)
    int bh = blockIdx.y;
    int h = bh & 1;
    const float4* gK = (const float4*)(g_k + bh * (TOK * 4));
    float4* s4K = (float4*)sK;
    for (int i = threadIdx.x; i < TOK; i += blockDim.x) s4K[i] = gK[i];
    const float* gP = pos + h * 4096;
    for (int i = threadIdx.x; i < 4096; i += blockDim.x) sP[i] = 0.5f * gP[i];
    __syncthreads();

    int warp = threadIdx.x >> 5, lane = threadIdx.x & 31;
    int qbase = blockIdx.x * 64 + warp * 8;
    int mi = qbase >> 6, nbase = qbase & 63;    // 8 consecutive queries share row mi

    float qv[8][4], m[8], l[8];
#pragma unroll
    for (int u = 0; u < 8; u++) {
        float4 qq = *(const float4*)(g_q + (bh * TOK + qbase + u) * 4);
        qv[u][0] = qq.x; qv[u][1] = qq.y; qv[u][2] = qq.z; qv[u][3] = qq.w;
        m[u] = -1e30f; l[u] = 0.f;
    }

    for (int j = lane; j < TOK; j += 32) {
        float4 kv = s4K[j];
        int mj = j >> 6, nj = j & 63;
        const float* prow = sP + (((mi - mj) & 63) << 6);
        int pc0 = (nbase - nj) & 63;
#pragma unroll
        for (int u = 0; u < 8; u++) {
            float s = prow[(pc0 + u) & 63];
            s = fmaf(qv[u][0], kv.x, s);
            s = fmaf(qv[u][1], kv.y, s);
            s = fmaf(qv[u][2], kv.z, s);
            s = fmaf(qv[u][3], kv.w, s);
            if (s > m[u]) {          // rarely taken after warm-up
                l[u] *= __expf(m[u] - s);
                m[u] = s;
            }
            l[u] += __expf(s - m[u]);
        }
    }

    // Merge (m,l) logsumexp partials across lanes, then lane 0 writes result
#pragma unroll
    for (int u = 0; u < 8; u++) {
#pragma unroll
        for (int off = 16; off > 0; off >>= 1) {
            float m2 = __shfl_down_sync(0xffffffffu, m[u], off);
            float l2 = __shfl_down_sync(0xffffffffu, l[u], off);
            float mn = fmaxf(m[u], m2);
            l[u] = l[u] * __expf(m[u] - mn) + l2 * __expf(m2 - mn);
            m[u] = mn;
        }
        if (lane == 0) {
            int t = qbase + u;
            // self-score: q_t . k_t + 0.5 * pos[h,0,0]   (P diag = R[h,0,0])
            float4 kv = s4K[t];
            float s = sP[0];
            s = fmaf(qv[u][0], kv.x, s);
            s = fmaf(qv[u][1], kv.y, s);
            s = fmaf(qv[u][2], kv.z, s);
            s = fmaf(qv[u][3], kv.w, s);
            float w = __expf(s - m[u]) / l[u];
            float4 vv = *(const float4*)(g_v + (bh * TOK + t) * 4);
            float4 o;
            o.x = w * vv.x; o.y = w * vv.y; o.z = w * vv.z; o.w = w * vv.w;
            *(float4*)(g_a + (bh * TOK + t) * 4) = o;
        }
    }
}

// ---------------- Stage 4: output projection Wo (8->8) + residual ----------------
__global__ void k_proj(const float* __restrict__ Wo) {
    __shared__ float sW[64];
    if (threadIdx.x < 64) sW[threadIdx.x] = Wo[threadIdx.x];
    __syncthreads();
    int p = blockIdx.x * blockDim.x + threadIdx.x;
    if (p >= TOT) return;
    int b = p >> 12, t = p & 4095;
    float vec[8];
#pragma unroll
    for (int h = 0; h < 2; h++) {
        float4 av = *(const float4*)(g_a + (((b << 1) | h) * TOK + t) * 4);
        vec[h * 4 + 0] = av.x; vec[h * 4 + 1] = av.y;
        vec[h * 4 + 2] = av.z; vec[h * 4 + 3] = av.w;
    }
    float acc[8];
#pragma unroll
    for (int c = 0; c < 8; c++) acc[c] = g_x1[p * 8 + c];
#pragma unroll
    for (int e = 0; e < 8; e++)
#pragma unroll
        for (int c = 0; c < 8; c++) acc[c] = fmaf(vec[e], sW[e * 8 + c], acc[c]);
#pragma unroll
    for (int c = 0; c < 8; c++) g_x2[p * 8 + c] = acc[c];
}

// ---------------- Stage 5: MLP1 1x1 conv (8->32) + gelu (input scaled by 1/sqrt(3)) ----------------
__global__ void k_mlp1(const float* __restrict__ W1, const float* __restrict__ b1) {
    __shared__ float sW[256];
    __shared__ float sb[32];
    for (int i = threadIdx.x; i < 256; i += blockDim.x) sW[i] = W1[i];
    if (threadIdx.x < 32) sb[threadIdx.x] = b1[threadIdx.x];
    __syncthreads();
    int p = blockIdx.x * blockDim.x + threadIdx.x;
    if (p >= TOT) return;
    float y[8];
#pragma unroll
    for (int c = 0; c < 8; c++) y[c] = g_x2[p * 8 + c] * 0.57735026918962576f;
#pragma unroll
    for (int e = 0; e < 32; e++) {
        float t = sb[e];
#pragma unroll
        for (int c = 0; c < 8; c++) t = fmaf(y[c], sW[c * 32 + e], t);
        g_t1[p * 32 + e] = gelu_f(t);
    }
}

// ---------------- Stage 6: depthwise 3x3 circular conv (32ch) + gelu ----------------
// one thread per (token, group-of-8-channels): 32768 threads
__global__ void k_mlp2(const float* __restrict__ W2, const float* __restrict__ b2) {
    __shared__ float sW[288];
    __shared__ float sb[32];
    for (int i = threadIdx.x; i < 288; i += blockDim.x) sW[i] = W2[i];
    if (threadIdx.x < 32) sb[threadIdx.x] = b2[threadIdx.x];
    __syncthreads();
    int tid = blockIdx.x * blockDim.x + threadIdx.x;
    if (tid >= TOT * 4) return;
    int p = tid >> 2, g4 = tid & 3, e0 = g4 * 8;
    int b = p >> 12, rem = p & 4095, i = rem >> 6, j = rem & 63;
    float acc[8];
#pragma unroll
    for (int ee = 0; ee < 8; ee++) acc[ee] = sb[e0 + ee];
#pragma unroll
    for (int di = 0; di < 3; di++) {
        int row = (i + di + 63) & 63;
#pragma unroll
        for (int dj = 0; dj < 3; dj++) {
            int col = (j + dj + 63) & 63;
            const float* tp = g_t1 + ((((b << 12) | (row << 6)) | col) * 32 + e0);
            const float* wp = sW + (di * 3 + dj) * 32 + e0;
#pragma unroll
            for (int ee = 0; ee < 8; ee++) acc[ee] = fmaf(tp[ee], wp[ee], acc[ee]);
        }
    }
#pragma unroll
    for (int ee = 0; ee < 8; ee++) g_t2[p * 32 + e0 + ee] = gelu_f(acc[ee]);
}

// ---------------- Stage 7: MLP3 1x1 conv (32->8) + bias + residual -> output ----------------
__global__ void k_mlp3(const float* __restrict__ W3, const float* __restrict__ b3,
                       float* __restrict__ out) {
    __shared__ float sW[256];   // [e][c]
    __shared__ float sb[8];
    for (int i = threadIdx.x; i < 256; i += blockDim.x) sW[i] = W3[i];
    if (threadIdx.x < 8) sb[threadIdx.x] = b3[threadIdx.x];
    __syncthreads();
    int p = blockIdx.x * blockDim.x + threadIdx.x;
    if (p >= TOT) return;
    float acc[8];
#pragma unroll
    for (int c = 0; c < 8; c++) acc[c] = sb[c] + g_x2[p * 8 + c];
#pragma unroll
    for (int e = 0; e < 32; e++) {
        float tv = g_t2[p * 32 + e];
#pragma unroll
        for (int c = 0; c < 8; c++) acc[c] = fmaf(tv, sW[e * 8 + c], acc[c]);
    }
#pragma unroll
    for (int c = 0; c < 8; c++) out[p * 8 + c] = acc[c];
}

extern "C" void kernel_launch(void* const* d_in, const int* in_sizes, int n_in,
                              void* d_out, int out_size) {
    const float* x      = (const float*)d_in[0];
    const float* conv_W = (const float*)d_in[1];
    const float* conv_b = (const float*)d_in[2];
    const float* Wq     = (const float*)d_in[3];
    const float* Wk     = (const float*)d_in[4];
    const float* Wv     = (const float*)d_in[5];
    const float* pos    = (const float*)d_in[6];
    const float* Wo     = (const float*)d_in[7];
    const float* m1W    = (const float*)d_in[8];
    const float* m1b    = (const float*)d_in[9];
    const float* m2W    = (const float*)d_in[10];
    const float* m2b    = (const float*)d_in[11];
    const float* m3W    = (const float*)d_in[12];
    const float* m3b    = (const float*)d_in[13];
    float* out = (float*)d_out;

    const int ATTN_SMEM = (16384 + 4096) * 4;   // 81920 bytes
    cudaFuncSetAttribute(k_attn, cudaFuncAttributeMaxDynamicSharedMemorySize, ATTN_SMEM);

    k_gelu<<<256, 256>>>(x);
    k_conv1<<<TOT / 256, 256>>>(x, conv_W, conv_b);
    k_qkv<<<TOT / 256, 256>>>(Wq, Wk, Wv);
    dim3 ag(64, 4);
    k_attn<<<ag, 256, ATTN_SMEM>>>(pos);
    k_proj<<<TOT / 256, 256>>>(Wo);
    k_mlp1<<<TOT / 256, 256>>>(m1W, m1b);
    k_mlp2<<<(TOT * 4) / 256, 256>>>(m2W, m2b);
    k_mlp3<<<TOT / 256, 256>>>(m3W, m3b, out);
}

// round 3
// speedup vs baseline: 1.8056x; 1.8056x over previous
#include <cuda_runtime.h>
#include <math.h>

// Problem constants: B=2, M=N=64, H=2, C=8, D=4
#define TOK  4096          // tokens per batch image (64*64)
#define TOT  8192          // total tokens (B*TOK)

#define SCALE_LOG2E 0.72134752044448170f   // 0.5 * log2(e)  (0.5 = 1/sqrt(d))
#define PPITCH 68                           // padded pos row pitch

// Scratch (allocation-free: __device__ globals)
__device__ float g_gelu[65536];    // gelu(x)
__device__ float g_x1[65536];      // after conv block + residual
__device__ float g_q[65536];       // [bh][t][d], pre-scaled by 0.5*log2e
__device__ float g_k[65536];
__device__ float g_v[65536];
__device__ float g_a[65536];       // attention output [bh][t][d]
__device__ float g_x2[65536];      // after attention + residual
__device__ float g_t1[262144];     // mlp hidden 1 (32 ch)
__device__ float g_t2[262144];     // mlp hidden 2 (32 ch)

// gelu(x) = x * sigmoid(2z), z = sqrt(2/pi)*(x + 0.044715 x^3)
__device__ __forceinline__ float gelu_f(float x) {
    float z2 = 1.5957691216057308f * fmaf(0.044715f, x * x * x, x);  // 2z
    return __fdividef(x, 1.0f + __expf(-z2));
}

// ---------------- Stage 0: gelu(x) ----------------
__global__ void k_gelu(const float* __restrict__ x) {
    int i = blockIdx.x * blockDim.x + threadIdx.x;
    if (i < 65536) g_gelu[i] = gelu_f(x[i]);
}

// ---------------- Stage 1: circular conv (8->8) + residual, then QKV ----------------
__global__ void __launch_bounds__(256) k_conv_qkv(
        const float* __restrict__ x, const float* __restrict__ W,
        const float* __restrict__ bias, const float* __restrict__ Wq,
        const float* __restrict__ Wk, const float* __restrict__ Wv) {
    __shared__ float sW[576];   // (3,3,8,8) HWIO
    __shared__ float sb[8];
    __shared__ float sQKV[192]; // Wq|Wk|Wv (each 8x8)
    for (int i = threadIdx.x; i < 576; i += blockDim.x) sW[i] = W[i];
    if (threadIdx.x < 8) sb[threadIdx.x] = bias[threadIdx.x];
    if (threadIdx.x < 64) {
        sQKV[threadIdx.x]       = Wq[threadIdx.x];
        sQKV[64 + threadIdx.x]  = Wk[threadIdx.x];
        sQKV[128 + threadIdx.x] = Wv[threadIdx.x];
    }
    __syncthreads();
    int p = blockIdx.x * blockDim.x + threadIdx.x;
    int b = p >> 12, rem = p & 4095, i = rem >> 6, j = rem & 63;
    float acc[8];
#pragma unroll
    for (int c = 0; c < 8; c++) acc[c] = sb[c] + x[p * 8 + c];
#pragma unroll
    for (int di = 0; di < 3; di++) {
        int row = (i + di + 63) & 63;
#pragma unroll
        for (int dj = 0; dj < 3; dj++) {
            int col = (j + dj + 63) & 63;
            const float* gp = g_gelu + ((((b << 12) | (row << 6)) | col) << 3);
            const float* wp = sW + (di * 3 + dj) * 64;
#pragma unroll
            for (int cin = 0; cin < 8; cin++) {
                float xv = gp[cin];
#pragma unroll
                for (int c = 0; c < 8; c++) acc[c] = fmaf(xv, wp[cin * 8 + c], acc[c]);
            }
        }
    }
#pragma unroll
    for (int c = 0; c < 8; c++) g_x1[p * 8 + c] = acc[c];
    // QKV: y = x1 / sqrt(2)
    float y[8];
#pragma unroll
    for (int c = 0; c < 8; c++) y[c] = acc[c] * 0.70710678118654752f;
    int t = p & 4095;
#pragma unroll
    for (int e = 0; e < 8; e++) {
        float qe = 0.f, ke = 0.f, ve = 0.f;
#pragma unroll
        for (int c = 0; c < 8; c++) {
            qe = fmaf(y[c], sQKV[c * 8 + e], qe);
            ke = fmaf(y[c], sQKV[64 + c * 8 + e], ke);
            ve = fmaf(y[c], sQKV[128 + c * 8 + e], ve);
        }
        int h = e >> 2, d = e & 3;
        int idx = (((b << 1) | h) * TOK + t) * 4 + d;
        g_q[idx] = qe * SCALE_LOG2E;   // fold 0.5*log2e
        g_k[idx] = ke;
        g_v[idx] = ve;
    }
}

// ---------------- Stage 2: attention (DIAGONAL: a_n = attn[n,n] * v_n) ----------------
// No-max streaming softmax denominator in log2 domain. 512 thr, 16 warps x 4 queries.
// smem: K (16384 f) + pos padded (64 x 68 f) = 82944 B -> 2 CTAs/SM.
__global__ void __launch_bounds__(512) k_attn(const float* __restrict__ pos) {
    extern __shared__ float smem[];
    float* sK = smem;              // 16384 floats (K as float4[4096])
    float* sP = smem + 16384;      // 64*PPITCH floats, pre-scaled by 0.5*log2e
    int bh = blockIdx.y;
    int h = bh & 1;
    const float4* gK = (const float4*)(g_k + bh * (TOK * 4));
    float4* s4K = (float4*)sK;
    for (int i = threadIdx.x; i < TOK; i += 512) s4K[i] = gK[i];
    const float* gP = pos + h * 4096;
    for (int i = threadIdx.x; i < 64 * PPITCH; i += 512) {
        int r = i / PPITCH, c = i % PPITCH;
        sP[i] = gP[(r << 6) + (c & 63)] * SCALE_LOG2E;
    }
    __syncthreads();

    int warp = threadIdx.x >> 5, lane = threadIdx.x & 31;
    int qbase = blockIdx.x * 64 + warp * 4;
    int mi = qbase >> 6, nbase = qbase & 63;    // 4 consecutive queries share row mi

    float qv[4][4], l[4];
#pragma unroll
    for (int u = 0; u < 4; u++) {
        float4 qq = *(const float4*)(g_q + (bh * TOK + qbase + u) * 4);
        qv[u][0] = qq.x; qv[u][1] = qq.y; qv[u][2] = qq.z; qv[u][3] = qq.w;
        l[u] = 0.f;
    }

#pragma unroll 2
    for (int j = lane; j < TOK; j += 32) {
        float4 kv = s4K[j];
        int mj = j >> 6, nj = j & 63;
        const float* prow = sP + ((mi - mj) & 63) * PPITCH;
        int pc0 = (nbase - nj) & 63;
#pragma unroll
        for (int u = 0; u < 4; u++) {
            float s = prow[pc0 + u];
            s = fmaf(qv[u][0], kv.x, s);
            s = fmaf(qv[u][1], kv.y, s);
            s = fmaf(qv[u][2], kv.z, s);
            s = fmaf(qv[u][3], kv.w, s);
            l[u] += exp2f(s);
        }
    }

    // Sum partials across lanes
#pragma unroll
    for (int u = 0; u < 4; u++) {
#pragma unroll
        for (int off = 16; off > 0; off >>= 1)
            l[u] += __shfl_xor_sync(0xffffffffu, l[u], off);
    }
    if (lane == 0) {
#pragma unroll
        for (int u = 0; u < 4; u++) {
            int t = qbase + u;
            // self-score: q_t . k_t + scaled pos[h,0,0]
            float4 kv = s4K[t];
            float s = sP[0];
            s = fmaf(qv[u][0], kv.x, s);
            s = fmaf(qv[u][1], kv.y, s);
            s = fmaf(qv[u][2], kv.z, s);
            s = fmaf(qv[u][3], kv.w, s);
            float w = __fdividef(exp2f(s), l[u]);
            float4 vv = *(const float4*)(g_v + (bh * TOK + t) * 4);
            float4 o;
            o.x = w * vv.x; o.y = w * vv.y; o.z = w * vv.z; o.w = w * vv.w;
            *(float4*)(g_a + (bh * TOK + t) * 4) = o;
        }
    }
}

// ---------------- Stage 3: Wo projection + residual, then MLP1 (8->32) + gelu ----------------
__global__ void __launch_bounds__(256) k_post1(const float* __restrict__ Wo,
                                               const float* __restrict__ W1,
                                               const float* __restrict__ b1) {
    __shared__ float sWo[64];
    __shared__ float sW1[256];
    __shared__ float sb1[32];
    if (threadIdx.x < 64) sWo[threadIdx.x] = Wo[threadIdx.x];
    for (int i = threadIdx.x; i < 256; i += blockDim.x) sW1[i] = W1[i];
    if (threadIdx.x < 32) sb1[threadIdx.x] = b1[threadIdx.x];
    __syncthreads();
    int p = blockIdx.x * blockDim.x + threadIdx.x;
    int b = p >> 12, t = p & 4095;
    float vec[8];
#pragma unroll
    for (int h = 0; h < 2; h++) {
        float4 av = *(const float4*)(g_a + (((b << 1) | h) * TOK + t) * 4);
        vec[h * 4 + 0] = av.x; vec[h * 4 + 1] = av.y;
        vec[h * 4 + 2] = av.z; vec[h * 4 + 3] = av.w;
    }
    float acc[8];
#pragma unroll
    for (int c = 0; c < 8; c++) acc[c] = g_x1[p * 8 + c];
#pragma unroll
    for (int e = 0; e < 8; e++)
#pragma unroll
        for (int c = 0; c < 8; c++) acc[c] = fmaf(vec[e], sWo[e * 8 + c], acc[c]);
#pragma unroll
    for (int c = 0; c < 8; c++) g_x2[p * 8 + c] = acc[c];
    // MLP1
    float y[8];
#pragma unroll
    for (int c = 0; c < 8; c++) y[c] = acc[c] * 0.57735026918962576f;  // 1/sqrt(3)
#pragma unroll
    for (int e = 0; e < 32; e++) {
        float v = sb1[e];
#pragma unroll
        for (int c = 0; c < 8; c++) v = fmaf(y[c], sW1[c * 32 + e], v);
        g_t1[p * 32 + e] = gelu_f(v);
    }
}

// ---------------- Stage 4: depthwise 3x3 circular conv (32ch) + gelu ----------------
__global__ void __launch_bounds__(256) k_mlp2(const float* __restrict__ W2,
                                              const float* __restrict__ b2) {
    __shared__ float sW[288];
    __shared__ float sb[32];
    for (int i = threadIdx.x; i < 288; i += blockDim.x) sW[i] = W2[i];
    if (threadIdx.x < 32) sb[threadIdx.x] = b2[threadIdx.x];
    __syncthreads();
    int tid = blockIdx.x * blockDim.x + threadIdx.x;
    int p = tid >> 2, g4 = tid & 3, e0 = g4 * 8;
    int b = p >> 12, rem = p & 4095, i = rem >> 6, j = rem & 63;
    float acc[8];
#pragma unroll
    for (int ee = 0; ee < 8; ee++) acc[ee] = sb[e0 + ee];
#pragma unroll
    for (int di = 0; di < 3; di++) {
        int row = (i + di + 63) & 63;
#pragma unroll
        for (int dj = 0; dj < 3; dj++) {
            int col = (j + dj + 63) & 63;
            const float* tp = g_t1 + ((((b << 12) | (row << 6)) | col) * 32 + e0);
            const float* wp = sW + (di * 3 + dj) * 32 + e0;
#pragma unroll
            for (int ee = 0; ee < 8; ee++) acc[ee] = fmaf(tp[ee], wp[ee], acc[ee]);
        }
    }
#pragma unroll
    for (int ee = 0; ee < 8; ee++) g_t2[p * 32 + e0 + ee] = gelu_f(acc[ee]);
}

// ---------------- Stage 5: MLP3 (32->8) + bias + residual -> output ----------------
__global__ void __launch_bounds__(256) k_mlp3(const float* __restrict__ W3,
                                              const float* __restrict__ b3,
                                              float* __restrict__ out) {
    __shared__ float sW[256];   // [e][c]
    __shared__ float sb[8];
    for (int i = threadIdx.x; i < 256; i += blockDim.x) sW[i] = W3[i];
    if (threadIdx.x < 8) sb[threadIdx.x] = b3[threadIdx.x];
    __syncthreads();
    int p = blockIdx.x * blockDim.x + threadIdx.x;
    float acc[8];
#pragma unroll
    for (int c = 0; c < 8; c++) acc[c] = sb[c] + g_x2[p * 8 + c];
#pragma unroll
    for (int e = 0; e < 32; e++) {
        float tv = g_t2[p * 32 + e];
#pragma unroll
        for (int c = 0; c < 8; c++) acc[c] = fmaf(tv, sW[e * 8 + c], acc[c]);
    }
#pragma unroll
    for (int c = 0; c < 8; c++) out[p * 8 + c] = acc[c];
}

extern "C" void kernel_launch(void* const* d_in, const int* in_sizes, int n_in,
                              void* d_out, int out_size) {
    const float* x      = (const float*)d_in[0];
    const float* conv_W = (const float*)d_in[1];
    const float* conv_b = (const float*)d_in[2];
    const float* Wq     = (const float*)d_in[3];
    const float* Wk     = (const float*)d_in[4];
    const float* Wv     = (const float*)d_in[5];
    const float* pos    = (const float*)d_in[6];
    const float* Wo     = (const float*)d_in[7];
    const float* m1W    = (const float*)d_in[8];
    const float* m1b    = (const float*)d_in[9];
    const float* m2W    = (const float*)d_in[10];
    const float* m2b    = (const float*)d_in[11];
    const float* m3W    = (const float*)d_in[12];
    const float* m3b    = (const float*)d_in[13];
    float* out = (float*)d_out;

    const int ATTN_SMEM = (16384 + 64 * PPITCH) * 4;   // 82944 bytes
    cudaFuncSetAttribute(k_attn, cudaFuncAttributeMaxDynamicSharedMemorySize, ATTN_SMEM);

    k_gelu<<<256, 256>>>(x);
    k_conv_qkv<<<TOT / 256, 256>>>(x, conv_W, conv_b, Wq, Wk, Wv);
    dim3 ag(64, 4);
    k_attn<<<ag, 512, ATTN_SMEM>>>(pos);
    k_post1<<<TOT / 256, 256>>>(Wo, m1W, m1b);
    k_mlp2<<<(TOT * 4) / 256, 256>>>(m2W, m2b);
    k_mlp3<<<TOT / 256, 256>>>(m3W, m3b, out);
}

// round 4
// speedup vs baseline: 2.6920x; 1.4909x over previous
#include <cuda_runtime.h>
#include <math.h>

// Problem constants: B=2, M=N=64, H=2, C=8, D=4
#define TOK  4096
#define TOT  8192

#define SCALE_LOG2E 0.72134752044448170f   // 0.5 * log2(e)
#define PPITCH 68

typedef unsigned long long u64;

// Scratch (allocation-free: __device__ globals)
__device__ float g_gelu[65536];
__device__ float g_x1[65536];
__device__ float g_q[65536];       // [bh][t][d], pre-scaled by 0.5*log2e
__device__ float g_k[65536];
__device__ float g_v[65536];
__device__ float g_a[65536];
__device__ float g_x2[65536];
__device__ float g_t1[262144];
__device__ float g_t2[262144];

__device__ __forceinline__ float gelu_f(float x) {
    float z2 = 1.5957691216057308f * fmaf(0.044715f, x * x * x, x);  // 2z
    return __fdividef(x, 1.0f + __expf(-z2));
}

__device__ __forceinline__ float ex2(float x) {
    float r; asm("ex2.approx.ftz.f32 %0, %1;" : "=f"(r) : "f"(x)); return r;
}
__device__ __forceinline__ u64 pk2(float lo, float hi) {
    u64 r; asm("mov.b64 %0, {%1,%2};" : "=l"(r) : "f"(lo), "f"(hi)); return r;
}
__device__ __forceinline__ void upk2(u64 v, float& lo, float& hi) {
    asm("mov.b64 {%0,%1}, %2;" : "=f"(lo), "=f"(hi) : "l"(v));
}
__device__ __forceinline__ u64 fma2(u64 a, u64 b, u64 c) {
    u64 d; asm("fma.rn.f32x2 %0, %1, %2, %3;" : "=l"(d) : "l"(a), "l"(b), "l"(c)); return d;
}
__device__ __forceinline__ u64 add2(u64 a, u64 b) {
    u64 d; asm("add.rn.f32x2 %0, %1, %2;" : "=l"(d) : "l"(a), "l"(b)); return d;
}

// ---------------- Stage 0: gelu(x) ----------------
__global__ void k_gelu(const float* __restrict__ x) {
    int i = blockIdx.x * blockDim.x + threadIdx.x;
    g_gelu[i] = gelu_f(x[i]);
}

// ---------------- Stage 1: circular conv (8->8) + residual + QKV ----------------
// 2 threads per token (split input channels 0-3 / 4-7), shuffle-combine. grid=128x128.
__global__ void __launch_bounds__(128) k_conv_qkv(
        const float* __restrict__ x, const float* __restrict__ W,
        const float* __restrict__ bias, const float* __restrict__ Wq,
        const float* __restrict__ Wk, const float* __restrict__ Wv) {
    __shared__ float sW[576];   // (3,3,8,8) HWIO
    __shared__ float sb[8];
    __shared__ float sQKV[192];
    for (int i = threadIdx.x; i < 576; i += 128) sW[i] = W[i];
    if (threadIdx.x < 8) sb[threadIdx.x] = bias[threadIdx.x];
    if (threadIdx.x < 64) {
        sQKV[threadIdx.x]       = Wq[threadIdx.x];
        sQKV[64 + threadIdx.x]  = Wk[threadIdx.x];
        sQKV[128 + threadIdx.x] = Wv[threadIdx.x];
    }
    __syncthreads();
    int gtid = blockIdx.x * 128 + threadIdx.x;
    int p = gtid >> 1, half = gtid & 1;
    int cin0 = half * 4;
    int b = p >> 12, rem = p & 4095, i = rem >> 6, j = rem & 63;
    float acc[8];
    if (half == 0) {
#pragma unroll
        for (int c = 0; c < 8; c++) acc[c] = sb[c] + x[p * 8 + c];
    } else {
#pragma unroll
        for (int c = 0; c < 8; c++) acc[c] = 0.f;
    }
#pragma unroll
    for (int di = 0; di < 3; di++) {
        int row = (i + di + 63) & 63;
#pragma unroll
        for (int dj = 0; dj < 3; dj++) {
            int col = (j + dj + 63) & 63;
            float4 xv4 = *(const float4*)(g_gelu + (((((b << 12) | (row << 6)) | col) << 3) + cin0));
            const float* wp = sW + (di * 3 + dj) * 64 + cin0 * 8;
            float xv[4] = {xv4.x, xv4.y, xv4.z, xv4.w};
#pragma unroll
            for (int ci = 0; ci < 4; ci++)
#pragma unroll
                for (int c = 0; c < 8; c++) acc[c] = fmaf(xv[ci], wp[ci * 8 + c], acc[c]);
        }
    }
    // combine halves (pair lanes)
#pragma unroll
    for (int c = 0; c < 8; c++) acc[c] += __shfl_xor_sync(0xffffffffu, acc[c], 1);

    float y[8];
#pragma unroll
    for (int c = 0; c < 8; c++) y[c] = acc[c] * 0.70710678118654752f;
    int t = p & 4095;
    if (half == 0) {
        // Q (scaled) and K
#pragma unroll
        for (int h = 0; h < 2; h++) {
            float q4[4], k4[4];
#pragma unroll
            for (int d = 0; d < 4; d++) {
                int e = h * 4 + d;
                float qe = 0.f, ke = 0.f;
#pragma unroll
                for (int c = 0; c < 8; c++) {
                    qe = fmaf(y[c], sQKV[c * 8 + e], qe);
                    ke = fmaf(y[c], sQKV[64 + c * 8 + e], ke);
                }
                q4[d] = qe * SCALE_LOG2E; k4[d] = ke;
            }
            int idx = (((b << 1) | h) * TOK + t) * 4;
            *(float4*)(g_q + idx) = make_float4(q4[0], q4[1], q4[2], q4[3]);
            *(float4*)(g_k + idx) = make_float4(k4[0], k4[1], k4[2], k4[3]);
        }
    } else {
        // V, and store x1
#pragma unroll
        for (int c = 0; c < 8; c++) g_x1[p * 8 + c] = acc[c];
#pragma unroll
        for (int h = 0; h < 2; h++) {
            float v4[4];
#pragma unroll
            for (int d = 0; d < 4; d++) {
                int e = h * 4 + d;
                float ve = 0.f;
#pragma unroll
                for (int c = 0; c < 8; c++) ve = fmaf(y[c], sQKV[128 + c * 8 + e], ve);
                v4[d] = ve;
            }
            int idx = (((b << 1) | h) * TOK + t) * 4;
            *(float4*)(g_v + idx) = make_float4(v4[0], v4[1], v4[2], v4[3]);
        }
    }
}

// ---------------- Stage 2: attention (DIAGONAL: a_n = attn[n,n] * v_n) ----------------
// Packed f32x2 score math; MUFU EX2 per score. 512 thr = 16 warps x 4 queries.
__global__ void __launch_bounds__(512) k_attn(const float* __restrict__ pos) {
    extern __shared__ float smem[];
    float* sK = smem;              // 16384 floats
    float* sP = smem + 16384;      // 64*PPITCH floats, pre-scaled
    int bh = blockIdx.y;
    int h = bh & 1;
    const float4* gK = (const float4*)(g_k + bh * (TOK * 4));
    float4* s4K = (float4*)sK;
    for (int i = threadIdx.x; i < TOK; i += 512) s4K[i] = gK[i];
    const float* gP = pos + h * 4096;
    for (int i = threadIdx.x; i < 64 * PPITCH; i += 512) {
        int r = i / PPITCH, c = i % PPITCH;
        sP[i] = gP[(r << 6) + (c & 63)] * SCALE_LOG2E;
    }
    __syncthreads();

    int warp = threadIdx.x >> 5, lane = threadIdx.x & 31;
    int qbase = blockIdx.x * 64 + warp * 4;
    int mi = qbase >> 6, nbase = qbase & 63;

    float qv[4][4];
#pragma unroll
    for (int u = 0; u < 4; u++) {
        float4 qq = *(const float4*)(g_q + (bh * TOK + qbase + u) * 4);
        qv[u][0] = qq.x; qv[u][1] = qq.y; qv[u][2] = qq.z; qv[u][3] = qq.w;
    }
    u64 q01[4], q23[4];
#pragma unroll
    for (int d = 0; d < 4; d++) {
        q01[d] = pk2(qv[0][d], qv[1][d]);
        q23[d] = pk2(qv[2][d], qv[3][d]);
    }
    u64 l01 = pk2(0.f, 0.f), l23 = pk2(0.f, 0.f);

#pragma unroll 2
    for (int j = lane; j < TOK; j += 32) {
        float4 kv = s4K[j];
        int mj = j >> 6, nj = j & 63;
        const float* prow = sP + ((mi - mj) & 63) * PPITCH;
        int pc0 = (nbase - nj) & 63;
        u64 s01 = pk2(prow[pc0], prow[pc0 + 1]);
        u64 s23 = pk2(prow[pc0 + 2], prow[pc0 + 3]);
        u64 kx = pk2(kv.x, kv.x), ky = pk2(kv.y, kv.y);
        u64 kz = pk2(kv.z, kv.z), kw = pk2(kv.w, kv.w);
        s01 = fma2(q01[0], kx, s01); s23 = fma2(q23[0], kx, s23);
        s01 = fma2(q01[1], ky, s01); s23 = fma2(q23[1], ky, s23);
        s01 = fma2(q01[2], kz, s01); s23 = fma2(q23[2], kz, s23);
        s01 = fma2(q01[3], kw, s01); s23 = fma2(q23[3], kw, s23);
        float a, b2, c, d;
        upk2(s01, a, b2); upk2(s23, c, d);
        l01 = add2(l01, pk2(ex2(a), ex2(b2)));
        l23 = add2(l23, pk2(ex2(c), ex2(d)));
    }

    float l[4];
    upk2(l01, l[0], l[1]); upk2(l23, l[2], l[3]);
#pragma unroll
    for (int u = 0; u < 4; u++) {
#pragma unroll
        for (int off = 16; off > 0; off >>= 1)
            l[u] += __shfl_xor_sync(0xffffffffu, l[u], off);
    }
    if (lane == 0) {
#pragma unroll
        for (int u = 0; u < 4; u++) {
            int t = qbase + u;
            float4 kv = s4K[t];
            float s = sP[0];
            s = fmaf(qv[u][0], kv.x, s);
            s = fmaf(qv[u][1], kv.y, s);
            s = fmaf(qv[u][2], kv.z, s);
            s = fmaf(qv[u][3], kv.w, s);
            float w = __fdividef(ex2(s), l[u]);
            float4 vv = *(const float4*)(g_v + (bh * TOK + t) * 4);
            *(float4*)(g_a + (bh * TOK + t) * 4) =
                make_float4(w * vv.x, w * vv.y, w * vv.z, w * vv.w);
        }
    }
}

// ---------------- Stage 3: Wo proj + residual, then MLP1 (8->32) + gelu ----------------
// 4 threads per token (each handles 8 of 32 MLP1 outputs). grid=128x256.
__global__ void __launch_bounds__(256) k_post1(const float* __restrict__ Wo,
                                               const float* __restrict__ W1,
                                               const float* __restrict__ b1) {
    __shared__ float sWo[64];
    __shared__ float sW1[256];
    __shared__ float sb1[32];
    if (threadIdx.x < 64) sWo[threadIdx.x] = Wo[threadIdx.x];
    for (int i = threadIdx.x; i < 256; i += 256) sW1[i] = W1[i];
    if (threadIdx.x < 32) sb1[threadIdx.x] = b1[threadIdx.x];
    __syncthreads();
    int gtid = blockIdx.x * 256 + threadIdx.x;
    int p = gtid >> 2, g4 = gtid & 3;
    int b = p >> 12, t = p & 4095;
    float vec[8];
#pragma unroll
    for (int h = 0; h < 2; h++) {
        float4 av = *(const float4*)(g_a + (((b << 1) | h) * TOK + t) * 4);
        vec[h * 4 + 0] = av.x; vec[h * 4 + 1] = av.y;
        vec[h * 4 + 2] = av.z; vec[h * 4 + 3] = av.w;
    }
    float acc[8];
#pragma unroll
    for (int c = 0; c < 8; c++) acc[c] = g_x1[p * 8 + c];
#pragma unroll
    for (int e = 0; e < 8; e++)
#pragma unroll
        for (int c = 0; c < 8; c++) acc[c] = fmaf(vec[e], sWo[e * 8 + c], acc[c]);
    if (g4 == 0) {
#pragma unroll
        for (int c = 0; c < 8; c++) g_x2[p * 8 + c] = acc[c];
    }
    float y[8];
#pragma unroll
    for (int c = 0; c < 8; c++) y[c] = acc[c] * 0.57735026918962576f;
    int e0 = g4 * 8;
#pragma unroll
    for (int ee = 0; ee < 8; ee++) {
        int e = e0 + ee;
        float v = sb1[e];
#pragma unroll
        for (int c = 0; c < 8; c++) v = fmaf(y[c], sW1[c * 32 + e], v);
        g_t1[p * 32 + e] = gelu_f(v);
    }
}

// ---------------- Stage 4: depthwise 3x3 circular conv (32ch) + gelu ----------------
// 8 threads per token (4 channels each). grid=256x256.
__global__ void __launch_bounds__(256) k_mlp2(const float* __restrict__ W2,
                                              const float* __restrict__ b2) {
    __shared__ float sW[288];
    __shared__ float sb[32];
    for (int i = threadIdx.x; i < 288; i += 256) sW[i] = W2[i];
    if (threadIdx.x < 32) sb[threadIdx.x] = b2[threadIdx.x];
    __syncthreads();
    int tid = blockIdx.x * 256 + threadIdx.x;
    int p = tid >> 3, g8 = tid & 7, e0 = g8 * 4;
    int b = p >> 12, rem = p & 4095, i = rem >> 6, j = rem & 63;
    float acc[4];
#pragma unroll
    for (int ee = 0; ee < 4; ee++) acc[ee] = sb[e0 + ee];
#pragma unroll
    for (int di = 0; di < 3; di++) {
        int row = (i + di + 63) & 63;
#pragma unroll
        for (int dj = 0; dj < 3; dj++) {
            int col = (j + dj + 63) & 63;
            float4 tv = *(const float4*)(g_t1 + ((((b << 12) | (row << 6)) | col) * 32 + e0));
            const float* wp = sW + (di * 3 + dj) * 32 + e0;
            acc[0] = fmaf(tv.x, wp[0], acc[0]);
            acc[1] = fmaf(tv.y, wp[1], acc[1]);
            acc[2] = fmaf(tv.z, wp[2], acc[2]);
            acc[3] = fmaf(tv.w, wp[3], acc[3]);
        }
    }
    float4 o;
    o.x = gelu_f(acc[0]); o.y = gelu_f(acc[1]);
    o.z = gelu_f(acc[2]); o.w = gelu_f(acc[3]);
    *(float4*)(g_t2 + p * 32 + e0) = o;
}

// ---------------- Stage 5: MLP3 (32->8) + bias + residual -> output ----------------
// 4 threads per token (2 output channels each). grid=128x256.
__global__ void __launch_bounds__(256) k_mlp3(const float* __restrict__ W3,
                                              const float* __restrict__ b3,
                                              float* __restrict__ out) {
    __shared__ float sW[256];   // [e][c]
    __shared__ float sb[8];
    for (int i = threadIdx.x; i < 256; i += 256) sW[i] = W3[i];
    if (threadIdx.x < 8) sb[threadIdx.x] = b3[threadIdx.x];
    __syncthreads();
    int gtid = blockIdx.x * 256 + threadIdx.x;
    int p = gtid >> 2, g4 = gtid & 3;
    int c0 = g4 * 2;
    float a0 = sb[c0]     + g_x2[p * 8 + c0];
    float a1 = sb[c0 + 1] + g_x2[p * 8 + c0 + 1];
    const float4* t4 = (const float4*)(g_t2 + p * 32);
#pragma unroll
    for (int q4 = 0; q4 < 8; q4++) {
        float4 tv = t4[q4];
        int e = q4 * 4;
        a0 = fmaf(tv.x, sW[(e + 0) * 8 + c0], a0);
        a1 = fmaf(tv.x, sW[(e + 0) * 8 + c0 + 1], a1);
        a0 = fmaf(tv.y, sW[(e + 1) * 8 + c0], a0);
        a1 = fmaf(tv.y, sW[(e + 1) * 8 + c0 + 1], a1);
        a0 = fmaf(tv.z, sW[(e + 2) * 8 + c0], a0);
        a1 = fmaf(tv.z, sW[(e + 2) * 8 + c0 + 1], a1);
        a0 = fmaf(tv.w, sW[(e + 3) * 8 + c0], a0);
        a1 = fmaf(tv.w, sW[(e + 3) * 8 + c0 + 1], a1);
    }
    *(float2*)(out + p * 8 + c0) = make_float2(a0, a1);
}

extern "C" void kernel_launch(void* const* d_in, const int* in_sizes, int n_in,
                              void* d_out, int out_size) {
    const float* x      = (const float*)d_in[0];
    const float* conv_W = (const float*)d_in[1];
    const float* conv_b = (const float*)d_in[2];
    const float* Wq     = (const float*)d_in[3];
    const float* Wk     = (const float*)d_in[4];
    const float* Wv     = (const float*)d_in[5];
    const float* pos    = (const float*)d_in[6];
    const float* Wo     = (const float*)d_in[7];
    const float* m1W    = (const float*)d_in[8];
    const float* m1b    = (const float*)d_in[9];
    const float* m2W    = (const float*)d_in[10];
    const float* m2b    = (const float*)d_in[11];
    const float* m3W    = (const float*)d_in[12];
    const float* m3b    = (const float*)d_in[13];
    float* out = (float*)d_out;

    const int ATTN_SMEM = (16384 + 64 * PPITCH) * 4;   // 82944 bytes
    cudaFuncSetAttribute(k_attn, cudaFuncAttributeMaxDynamicSharedMemorySize, ATTN_SMEM);

    k_gelu<<<256, 256>>>(x);
    k_conv_qkv<<<128, 128>>>(x, conv_W, conv_b, Wq, Wk, Wv);
    dim3 ag(64, 4);
    k_attn<<<ag, 512, ATTN_SMEM>>>(pos);
    k_post1<<<128, 256>>>(Wo, m1W, m1b);
    k_mlp2<<<256, 256>>>(m2W, m2b);
    k_mlp3<<<128, 256>>>(m3W, m3b, out);
}

// round 5
// speedup vs baseline: 2.8180x; 1.0468x over previous
#include <cuda_runtime.h>
#include <cuda_fp16.h>
#include <math.h>

// Problem constants: B=2, M=N=64, H=2, C=8, D=4
#define TOK  4096
#define TOT  8192

#define SCALE_LOG2E 0.72134752044448170f   // 0.5 * log2(e)
#define PPITCH 68

typedef unsigned long long u64;

// Scratch (allocation-free: __device__ globals)
__device__ float g_gelu[65536];
__device__ float g_x1[65536];
__device__ float g_q[65536];       // [bh][t][d], pre-scaled by 0.5*log2e
__device__ float g_k[65536];
__device__ float g_v[65536];
__device__ float g_a[65536];
__device__ float g_x2[65536];
__device__ float g_t1[262144];
__device__ float g_t2[262144];

__device__ __forceinline__ float gelu_f(float x) {
    float z2 = 1.5957691216057308f * fmaf(0.044715f, x * x * x, x);  // 2z
    return __fdividef(x, 1.0f + __expf(-z2));
}

__device__ __forceinline__ float ex2(float x) {
    float r; asm("ex2.approx.ftz.f32 %0, %1;" : "=f"(r) : "f"(x)); return r;
}
__device__ __forceinline__ __half2 h2ex2(__half2 x) {
    __half2 r;
    asm("ex2.approx.f16x2 %0, %1;"
        : "=r"(*reinterpret_cast<unsigned*>(&r))
        : "r"(*reinterpret_cast<const unsigned*>(&x)));
    return r;
}
__device__ __forceinline__ u64 pk2(float lo, float hi) {
    u64 r; asm("mov.b64 %0, {%1,%2};" : "=l"(r) : "f"(lo), "f"(hi)); return r;
}
__device__ __forceinline__ void upk2(u64 v, float& lo, float& hi) {
    asm("mov.b64 {%0,%1}, %2;" : "=f"(lo), "=f"(hi) : "l"(v));
}
__device__ __forceinline__ u64 fma2(u64 a, u64 b, u64 c) {
    u64 d; asm("fma.rn.f32x2 %0, %1, %2, %3;" : "=l"(d) : "l"(a), "l"(b), "l"(c)); return d;
}

// ---------------- Stage 0: gelu(x) ----------------
__global__ void k_gelu(const float* __restrict__ x) {
    int i = blockIdx.x * blockDim.x + threadIdx.x;
    g_gelu[i] = gelu_f(x[i]);
}

// ---------------- Stage 1: circular conv (8->8) + residual + QKV ----------------
// 4 threads per token (2 input channels each), 2 shfl-combine rounds. grid=256x128.
__global__ void __launch_bounds__(128) k_conv_qkv(
        const float* __restrict__ x, const float* __restrict__ W,
        const float* __restrict__ bias, const float* __restrict__ Wq,
        const float* __restrict__ Wk, const float* __restrict__ Wv) {
    __shared__ float sW[576];   // (3,3,8,8) HWIO
    __shared__ float sb[8];
    __shared__ float sQKV[192];
    for (int i = threadIdx.x; i < 576; i += 128) sW[i] = W[i];
    if (threadIdx.x < 8) sb[threadIdx.x] = bias[threadIdx.x];
    if (threadIdx.x < 64) {
        sQKV[threadIdx.x]       = Wq[threadIdx.x];
        sQKV[64 + threadIdx.x]  = Wk[threadIdx.x];
        sQKV[128 + threadIdx.x] = Wv[threadIdx.x];
    }
    __syncthreads();
    int gtid = blockIdx.x * 128 + threadIdx.x;
    int p = gtid >> 2, quarter = gtid & 3;
    int cin0 = quarter * 2;
    int b = p >> 12, rem = p & 4095, i = rem >> 6, j = rem & 63;
    float acc[8];
    if (quarter == 0) {
#pragma unroll
        for (int c = 0; c < 8; c++) acc[c] = sb[c] + x[p * 8 + c];
    } else {
#pragma unroll
        for (int c = 0; c < 8; c++) acc[c] = 0.f;
    }
#pragma unroll
    for (int di = 0; di < 3; di++) {
        int row = (i + di + 63) & 63;
#pragma unroll
        for (int dj = 0; dj < 3; dj++) {
            int col = (j + dj + 63) & 63;
            float2 xv2 = *(const float2*)(g_gelu + (((((b << 12) | (row << 6)) | col) << 3) + cin0));
            const float* wp = sW + (di * 3 + dj) * 64 + cin0 * 8;
#pragma unroll
            for (int c = 0; c < 8; c++) acc[c] = fmaf(xv2.x, wp[c], acc[c]);
#pragma unroll
            for (int c = 0; c < 8; c++) acc[c] = fmaf(xv2.y, wp[8 + c], acc[c]);
        }
    }
#pragma unroll
    for (int c = 0; c < 8; c++) acc[c] += __shfl_xor_sync(0xffffffffu, acc[c], 1);
#pragma unroll
    for (int c = 0; c < 8; c++) acc[c] += __shfl_xor_sync(0xffffffffu, acc[c], 2);

    int t = p & 4095;
    if (quarter == 0) {
        *(float4*)(g_x1 + p * 8)     = make_float4(acc[0], acc[1], acc[2], acc[3]);
        *(float4*)(g_x1 + p * 8 + 4) = make_float4(acc[4], acc[5], acc[6], acc[7]);
    } else {
        float y[8];
#pragma unroll
        for (int c = 0; c < 8; c++) y[c] = acc[c] * 0.70710678118654752f;
        const float* wsel = sQKV + (quarter - 1) * 64;
        float scale = (quarter == 1) ? SCALE_LOG2E : 1.0f;
        float* gdst = (quarter == 1) ? g_q : (quarter == 2) ? g_k : g_v;
#pragma unroll
        for (int h = 0; h < 2; h++) {
            float o4[4];
#pragma unroll
            for (int d = 0; d < 4; d++) {
                int e = h * 4 + d;
                float v = 0.f;
#pragma unroll
                for (int c = 0; c < 8; c++) v = fmaf(y[c], wsel[c * 8 + e], v);
                o4[d] = v * scale;
            }
            *(float4*)(gdst + ((((b << 1) | h) * TOK + t) << 2)) =
                make_float4(o4[0], o4[1], o4[2], o4[3]);
        }
    }
}

// ---------------- Stage 2: attention (DIAGONAL: a_n = attn[n,n] * v_n) ----------------
// mj-outer loop; lane owns fixed (nja, njb). f32x2 score FMAs, f16x2 EX2 (2 exps/MUFU),
// f16x2 partial sums flushed to f32 every 8 mj (16 terms). pos rows doubled (128 rows).
__global__ void __launch_bounds__(512, 2) k_attn(const float* __restrict__ pos) {
    extern __shared__ float smem[];
    float* sK = smem;                    // 16384 floats
    float* sP = smem + 16384;            // 128 * PPITCH floats (rows doubled), pre-scaled
    int bh = blockIdx.y;
    int h = bh & 1;
    const float4* gK = (const float4*)(g_k + bh * (TOK * 4));
    float4* s4K = (float4*)sK;
    for (int i = threadIdx.x; i < TOK; i += 512) s4K[i] = gK[i];
    const float* gP = pos + h * 4096;
    for (int i = threadIdx.x; i < 128 * PPITCH; i += 512) {
        int r = i / PPITCH, c = i - r * PPITCH;
        sP[i] = gP[((r & 63) << 6) + (c & 63)] * SCALE_LOG2E;
    }
    __syncthreads();

    int warp = threadIdx.x >> 5, lane = threadIdx.x & 31;
    int qbase = blockIdx.x * 64 + warp * 4;
    int mi = qbase >> 6, nbase = qbase & 63;

    float qv[4][4];
#pragma unroll
    for (int u = 0; u < 4; u++) {
        float4 qq = *(const float4*)(g_q + (bh * TOK + qbase + u) * 4);
        qv[u][0] = qq.x; qv[u][1] = qq.y; qv[u][2] = qq.z; qv[u][3] = qq.w;
    }
    u64 q01[4], q23[4];
#pragma unroll
    for (int d = 0; d < 4; d++) {
        q01[d] = pk2(qv[0][d], qv[1][d]);
        q23[d] = pk2(qv[2][d], qv[3][d]);
    }

    int pc0a = (nbase - lane) & 63;
    int pc0b = (nbase - lane - 32) & 63;
    const float* pA = sP + (mi + 64) * PPITCH + pc0a;
    const float* pB = sP + (mi + 64) * PPITCH + pc0b;
    const float4* kp = s4K + lane;

    float l0 = 0.f, l1 = 0.f, l2 = 0.f, l3 = 0.f;
#pragma unroll 1
    for (int blk = 0; blk < 8; blk++) {
        __half2 acc01 = __floats2half2_rn(0.f, 0.f);
        __half2 acc23 = __floats2half2_rn(0.f, 0.f);
#pragma unroll
        for (int it = 0; it < 8; it++) {
            const float* ra = pA - it * PPITCH;
            const float* rb = pB - it * PPITCH;
            float4 kva = kp[it * 64];
            float4 kvb = kp[it * 64 + 32];
            // class a (keys nj = lane)
            {
                u64 kx = pk2(kva.x, kva.x), ky = pk2(kva.y, kva.y);
                u64 kz = pk2(kva.z, kva.z), kw = pk2(kva.w, kva.w);
                u64 s01 = pk2(ra[0], ra[1]);
                u64 s23 = pk2(ra[2], ra[3]);
                s01 = fma2(q01[0], kx, s01); s23 = fma2(q23[0], kx, s23);
                s01 = fma2(q01[1], ky, s01); s23 = fma2(q23[1], ky, s23);
                s01 = fma2(q01[2], kz, s01); s23 = fma2(q23[2], kz, s23);
                s01 = fma2(q01[3], kw, s01); s23 = fma2(q23[3], kw, s23);
                float a0, a1, a2, a3;
                upk2(s01, a0, a1); upk2(s23, a2, a3);
                acc01 = __hadd2(acc01, h2ex2(__floats2half2_rn(a0, a1)));
                acc23 = __hadd2(acc23, h2ex2(__floats2half2_rn(a2, a3)));
            }
            // class b (keys nj = lane + 32)
            {
                u64 kx = pk2(kvb.x, kvb.x), ky = pk2(kvb.y, kvb.y);
                u64 kz = pk2(kvb.z, kvb.z), kw = pk2(kvb.w, kvb.w);
                u64 s01 = pk2(rb[0], rb[1]);
                u64 s23 = pk2(rb[2], rb[3]);
                s01 = fma2(q01[0], kx, s01); s23 = fma2(q23[0], kx, s23);
                s01 = fma2(q01[1], ky, s01); s23 = fma2(q23[1], ky, s23);
                s01 = fma2(q01[2], kz, s01); s23 = fma2(q23[2], kz, s23);
                s01 = fma2(q01[3], kw, s01); s23 = fma2(q23[3], kw, s23);
                float b0, b1, b2, b3;
                upk2(s01, b0, b1); upk2(s23, b2, b3);
                acc01 = __hadd2(acc01, h2ex2(__floats2half2_rn(b0, b1)));
                acc23 = __hadd2(acc23, h2ex2(__floats2half2_rn(b2, b3)));
            }
        }
        pA -= 8 * PPITCH; pB -= 8 * PPITCH; kp += 8 * 64;
        l0 += __low2float(acc01); l1 += __high2float(acc01);
        l2 += __low2float(acc23); l3 += __high2float(acc23);
    }

    float l[4] = {l0, l1, l2, l3};
#pragma unroll
    for (int u = 0; u < 4; u++) {
#pragma unroll
        for (int off = 16; off > 0; off >>= 1)
            l[u] += __shfl_xor_sync(0xffffffffu, l[u], off);
    }
    if (lane == 0) {
#pragma unroll
        for (int u = 0; u < 4; u++) {
            int t = qbase + u;
            float4 kv = s4K[t];
            float s = sP[0];   // diagonal pos bias = scaled R[h,0,0]
            s = fmaf(qv[u][0], kv.x, s);
            s = fmaf(qv[u][1], kv.y, s);
            s = fmaf(qv[u][2], kv.z, s);
            s = fmaf(qv[u][3], kv.w, s);
            float w = __fdividef(ex2(s), l[u]);
            float4 vv = *(const float4*)(g_v + (bh * TOK + t) * 4);
            *(float4*)(g_a + (bh * TOK + t) * 4) =
                make_float4(w * vv.x, w * vv.y, w * vv.z, w * vv.w);
        }
    }
}

// ---------------- Stage 3: Wo proj + residual, then MLP1 (8->32) + gelu ----------------
// 8 threads per token (4 of 32 mlp1 outputs each). grid=256x256.
__global__ void __launch_bounds__(256) k_post1(const float* __restrict__ Wo,
                                               const float* __restrict__ W1,
                                               const float* __restrict__ b1) {
    __shared__ float sWo[64];
    __shared__ float sW1[256];
    __shared__ float sb1[32];
    if (threadIdx.x < 64) sWo[threadIdx.x] = Wo[threadIdx.x];
    sW1[threadIdx.x] = W1[threadIdx.x];
    if (threadIdx.x < 32) sb1[threadIdx.x] = b1[threadIdx.x];
    __syncthreads();
    int gtid = blockIdx.x * 256 + threadIdx.x;
    int p = gtid >> 3, sub = gtid & 7;
    int b = p >> 12, t = p & 4095;
    float vec[8];
#pragma unroll
    for (int h = 0; h < 2; h++) {
        float4 av = *(const float4*)(g_a + (((b << 1) | h) * TOK + t) * 4);
        vec[h * 4 + 0] = av.x; vec[h * 4 + 1] = av.y;
        vec[h * 4 + 2] = av.z; vec[h * 4 + 3] = av.w;
    }
    float acc[8];
    float4 x1a = *(const float4*)(g_x1 + p * 8);
    float4 x1b = *(const float4*)(g_x1 + p * 8 + 4);
    acc[0] = x1a.x; acc[1] = x1a.y; acc[2] = x1a.z; acc[3] = x1a.w;
    acc[4] = x1b.x; acc[5] = x1b.y; acc[6] = x1b.z; acc[7] = x1b.w;
#pragma unroll
    for (int e = 0; e < 8; e++)
#pragma unroll
        for (int c = 0; c < 8; c++) acc[c] = fmaf(vec[e], sWo[e * 8 + c], acc[c]);
    if (sub == 0) {
        *(float4*)(g_x2 + p * 8)     = make_float4(acc[0], acc[1], acc[2], acc[3]);
        *(float4*)(g_x2 + p * 8 + 4) = make_float4(acc[4], acc[5], acc[6], acc[7]);
    }
    float y[8];
#pragma unroll
    for (int c = 0; c < 8; c++) y[c] = acc[c] * 0.57735026918962576f;
    int e0 = sub * 4;
    float o[4];
#pragma unroll
    for (int ee = 0; ee < 4; ee++) {
        int e = e0 + ee;
        float v = sb1[e];
#pragma unroll
        for (int c = 0; c < 8; c++) v = fmaf(y[c], sW1[c * 32 + e], v);
        o[ee] = gelu_f(v);
    }
    *(float4*)(g_t1 + p * 32 + e0) = make_float4(o[0], o[1], o[2], o[3]);
}

// ---------------- Stage 4: depthwise 3x3 circular conv (32ch) + gelu ----------------
// 8 threads per token (4 channels each). grid=256x256.
__global__ void __launch_bounds__(256) k_mlp2(const float* __restrict__ W2,
                                              const float* __restrict__ b2) {
    __shared__ float sW[288];
    __shared__ float sb[32];
    for (int i = threadIdx.x; i < 288; i += 256) sW[i] = W2[i];
    if (threadIdx.x < 32) sb[threadIdx.x] = b2[threadIdx.x];
    __syncthreads();
    int tid = blockIdx.x * 256 + threadIdx.x;
    int p = tid >> 3, g8 = tid & 7, e0 = g8 * 4;
    int b = p >> 12, rem = p & 4095, i = rem >> 6, j = rem & 63;
    float acc[4];
#pragma unroll
    for (int ee = 0; ee < 4; ee++) acc[ee] = sb[e0 + ee];
#pragma unroll
    for (int di = 0; di < 3; di++) {
        int row = (i + di + 63) & 63;
#pragma unroll
        for (int dj = 0; dj < 3; dj++) {
            int col = (j + dj + 63) & 63;
            float4 tv = *(const float4*)(g_t1 + ((((b << 12) | (row << 6)) | col) * 32 + e0));
            const float* wp = sW + (di * 3 + dj) * 32 + e0;
            acc[0] = fmaf(tv.x, wp[0], acc[0]);
            acc[1] = fmaf(tv.y, wp[1], acc[1]);
            acc[2] = fmaf(tv.z, wp[2], acc[2]);
            acc[3] = fmaf(tv.w, wp[3], acc[3]);
        }
    }
    float4 o;
    o.x = gelu_f(acc[0]); o.y = gelu_f(acc[1]);
    o.z = gelu_f(acc[2]); o.w = gelu_f(acc[3]);
    *(float4*)(g_t2 + p * 32 + e0) = o;
}

// ---------------- Stage 5: MLP3 (32->8) + bias + residual -> output ----------------
// 8 threads per token (1 output channel each). grid=256x256, perfectly coalesced store.
__global__ void __launch_bounds__(256) k_mlp3(const float* __restrict__ W3,
                                              const float* __restrict__ b3,
                                              float* __restrict__ out) {
    __shared__ float sW[256];   // [e][c]
    __shared__ float sb[8];
    sW[threadIdx.x] = W3[threadIdx.x];
    if (threadIdx.x < 8) sb[threadIdx.x] = b3[threadIdx.x];
    __syncthreads();
    int gtid = blockIdx.x * 256 + threadIdx.x;
    int p = gtid >> 3, c = gtid & 7;
    float a = sb[c] + g_x2[gtid];
    const float4* t4 = (const float4*)(g_t2 + p * 32);
#pragma unroll
    for (int q4 = 0; q4 < 8; q4++) {
        float4 tv = t4[q4];
        int e = q4 * 4;
        a = fmaf(tv.x, sW[(e + 0) * 8 + c], a);
        a = fmaf(tv.y, sW[(e + 1) * 8 + c], a);
        a = fmaf(tv.z, sW[(e + 2) * 8 + c], a);
        a = fmaf(tv.w, sW[(e + 3) * 8 + c], a);
    }
    out[gtid] = a;
}

extern "C" void kernel_launch(void* const* d_in, const int* in_sizes, int n_in,
                              void* d_out, int out_size) {
    const float* x      = (const float*)d_in[0];
    const float* conv_W = (const float*)d_in[1];
    const float* conv_b = (const float*)d_in[2];
    const float* Wq     = (const float*)d_in[3];
    const float* Wk     = (const float*)d_in[4];
    const float* Wv     = (const float*)d_in[5];
    const float* pos    = (const float*)d_in[6];
    const float* Wo     = (const float*)d_in[7];
    const float* m1W    = (const float*)d_in[8];
    const float* m1b    = (const float*)d_in[9];
    const float* m2W    = (const float*)d_in[10];
    const float* m2b    = (const float*)d_in[11];
    const float* m3W    = (const float*)d_in[12];
    const float* m3b    = (const float*)d_in[13];
    float* out = (float*)d_out;

    const int ATTN_SMEM = (16384 + 128 * PPITCH) * 4;   // 100352 bytes
    cudaFuncSetAttribute(k_attn, cudaFuncAttributeMaxDynamicSharedMemorySize, ATTN_SMEM);

    k_gelu<<<256, 256>>>(x);
    k_conv_qkv<<<256, 128>>>(x, conv_W, conv_b, Wq, Wk, Wv);
    dim3 ag(64, 4);
    k_attn<<<ag, 512, ATTN_SMEM>>>(pos);
    k_post1<<<256, 256>>>(Wo, m1W, m1b);
    k_mlp2<<<256, 256>>>(m2W, m2b);
    k_mlp3<<<256, 256>>>(m3W, m3b, out);
}

// round 6
// speedup vs baseline: 2.8662x; 1.0171x over previous
#include <cuda_runtime.h>
#include <cuda_fp16.h>
#include <math.h>

// Problem constants: B=2, M=N=64, H=2, C=8, D=4
#define TOK  4096
#define TOT  8192

#define SCALE_LOG2E 0.72134752044448170f   // 0.5 * log2(e)
#define PPITCH 72                           // padded pos row pitch (needs 64+7)

typedef unsigned long long u64;

// Scratch (allocation-free: __device__ globals)
__device__ float g_gelu[65536];
__device__ float g_x1[65536];
__device__ float g_q[65536];       // [bh][t][d], pre-scaled by 0.5*log2e
__device__ float g_k[65536];
__device__ float g_v[65536];
__device__ float g_a[65536];
__device__ float g_x2[65536];
__device__ float g_t1[262144];

__device__ __forceinline__ float gelu_f(float x) {
    float z2 = 1.5957691216057308f * fmaf(0.044715f, x * x * x, x);  // 2z
    return __fdividef(x, 1.0f + __expf(-z2));
}

__device__ __forceinline__ float ex2(float x) {
    float r; asm("ex2.approx.ftz.f32 %0, %1;" : "=f"(r) : "f"(x)); return r;
}
__device__ __forceinline__ __half2 h2ex2(__half2 x) {
    __half2 r;
    asm("ex2.approx.f16x2 %0, %1;"
        : "=r"(*reinterpret_cast<unsigned*>(&r))
        : "r"(*reinterpret_cast<const unsigned*>(&x)));
    return r;
}
__device__ __forceinline__ u64 pk2(float lo, float hi) {
    u64 r; asm("mov.b64 %0, {%1,%2};" : "=l"(r) : "f"(lo), "f"(hi)); return r;
}
__device__ __forceinline__ void upk2(u64 v, float& lo, float& hi) {
    asm("mov.b64 {%0,%1}, %2;" : "=f"(lo), "=f"(hi) : "l"(v));
}
__device__ __forceinline__ u64 fma2(u64 a, u64 b, u64 c) {
    u64 d; asm("fma.rn.f32x2 %0, %1, %2, %3;" : "=l"(d) : "l"(a), "l"(b), "l"(c)); return d;
}

// ---------------- Stage 0: gelu(x) ----------------
__global__ void k_gelu(const float* __restrict__ x) {
    int i = blockIdx.x * blockDim.x + threadIdx.x;
    g_gelu[i] = gelu_f(x[i]);
}

// ---------------- Stage 1: circular conv (8->8) + residual + QKV ----------------
// 4 threads per token (2 input channels each), 2 shfl-combine rounds. grid=256x128.
__global__ void __launch_bounds__(128) k_conv_qkv(
        const float* __restrict__ x, const float* __restrict__ W,
        const float* __restrict__ bias, const float* __restrict__ Wq,
        const float* __restrict__ Wk, const float* __restrict__ Wv) {
    __shared__ float sW[576];   // (3,3,8,8) HWIO
    __shared__ float sb[8];
    __shared__ float sQKV[192];
    for (int i = threadIdx.x; i < 576; i += 128) sW[i] = W[i];
    if (threadIdx.x < 8) sb[threadIdx.x] = bias[threadIdx.x];
    if (threadIdx.x < 64) {
        sQKV[threadIdx.x]       = Wq[threadIdx.x];
        sQKV[64 + threadIdx.x]  = Wk[threadIdx.x];
        sQKV[128 + threadIdx.x] = Wv[threadIdx.x];
    }
    __syncthreads();
    int gtid = blockIdx.x * 128 + threadIdx.x;
    int p = gtid >> 2, quarter = gtid & 3;
    int cin0 = quarter * 2;
    int b = p >> 12, rem = p & 4095, i = rem >> 6, j = rem & 63;
    float acc[8];
    if (quarter == 0) {
#pragma unroll
        for (int c = 0; c < 8; c++) acc[c] = sb[c] + x[p * 8 + c];
    } else {
#pragma unroll
        for (int c = 0; c < 8; c++) acc[c] = 0.f;
    }
#pragma unroll
    for (int di = 0; di < 3; di++) {
        int row = (i + di + 63) & 63;
#pragma unroll
        for (int dj = 0; dj < 3; dj++) {
            int col = (j + dj + 63) & 63;
            float2 xv2 = *(const float2*)(g_gelu + (((((b << 12) | (row << 6)) | col) << 3) + cin0));
            const float* wp = sW + (di * 3 + dj) * 64 + cin0 * 8;
#pragma unroll
            for (int c = 0; c < 8; c++) acc[c] = fmaf(xv2.x, wp[c], acc[c]);
#pragma unroll
            for (int c = 0; c < 8; c++) acc[c] = fmaf(xv2.y, wp[8 + c], acc[c]);
        }
    }
#pragma unroll
    for (int c = 0; c < 8; c++) acc[c] += __shfl_xor_sync(0xffffffffu, acc[c], 1);
#pragma unroll
    for (int c = 0; c < 8; c++) acc[c] += __shfl_xor_sync(0xffffffffu, acc[c], 2);

    int t = p & 4095;
    if (quarter == 0) {
        *(float4*)(g_x1 + p * 8)     = make_float4(acc[0], acc[1], acc[2], acc[3]);
        *(float4*)(g_x1 + p * 8 + 4) = make_float4(acc[4], acc[5], acc[6], acc[7]);
    } else {
        float y[8];
#pragma unroll
        for (int c = 0; c < 8; c++) y[c] = acc[c] * 0.70710678118654752f;
        const float* wsel = sQKV + (quarter - 1) * 64;
        float scale = (quarter == 1) ? SCALE_LOG2E : 1.0f;
        float* gdst = (quarter == 1) ? g_q : (quarter == 2) ? g_k : g_v;
#pragma unroll
        for (int h = 0; h < 2; h++) {
            float o4[4];
#pragma unroll
            for (int d = 0; d < 4; d++) {
                int e = h * 4 + d;
                float v = 0.f;
#pragma unroll
                for (int c = 0; c < 8; c++) v = fmaf(y[c], wsel[c * 8 + e], v);
                o4[d] = v * scale;
            }
            *(float4*)(gdst + ((((b << 1) | h) * TOK + t) << 2)) =
                make_float4(o4[0], o4[1], o4[2], o4[3]);
        }
    }
}

// ---------------- Stage 2: attention (DIAGONAL: a_n = attn[n,n] * v_n) ----------------
// 8 warps x 8 queries; lane owns keys nj=lane (class a) and nj=lane+32 (class b),
// iterating all 64 mj rows. f32x2 score FMAs, f16x2 EX2, f16 partials flushed
// to f32 every 8 rows. grid=(64 mi-rows, 4 bh), 256 threads, 2 CTAs/SM.
__global__ void __launch_bounds__(256, 2) k_attn(const float* __restrict__ pos) {
    extern __shared__ float smem[];
    float* sK = smem;                    // 16384 floats
    float* sP = smem + 16384;            // 128 * PPITCH floats (rows doubled), pre-scaled
    int bh = blockIdx.y;
    int h = bh & 1;
    const float4* gK = (const float4*)(g_k + bh * (TOK * 4));
    float4* s4K = (float4*)sK;
    for (int i = threadIdx.x; i < TOK; i += 256) s4K[i] = gK[i];
    const float* gP = pos + h * 4096;
    for (int i = threadIdx.x; i < 128 * PPITCH; i += 256) {
        int r = i / PPITCH, c = i - r * PPITCH;
        sP[i] = gP[((r & 63) << 6) + (c & 63)] * SCALE_LOG2E;
    }
    __syncthreads();

    int warp = threadIdx.x >> 5, lane = threadIdx.x & 31;
    int mi = blockIdx.x;
    int nbase = warp * 8;
    int qbase = (mi << 6) | nbase;

    float qv[8][4];
#pragma unroll
    for (int u = 0; u < 8; u++) {
        float4 qq = *(const float4*)(g_q + (bh * TOK + qbase + u) * 4);
        qv[u][0] = qq.x; qv[u][1] = qq.y; qv[u][2] = qq.z; qv[u][3] = qq.w;
    }
    u64 qp[4][4];   // [query-pair][d]
#pragma unroll
    for (int pr = 0; pr < 4; pr++)
#pragma unroll
        for (int d = 0; d < 4; d++)
            qp[pr][d] = pk2(qv[2 * pr][d], qv[2 * pr + 1][d]);

    int pc0a = (nbase - lane) & 63;
    int pc0b = (nbase - lane - 32) & 63;
    const float* pA = sP + (mi + 64) * PPITCH + pc0a;
    const float* pB = sP + (mi + 64) * PPITCH + pc0b;
    const float4* kp = s4K + lane;

    float l[8];
#pragma unroll
    for (int u = 0; u < 8; u++) l[u] = 0.f;

#pragma unroll 1
    for (int blk = 0; blk < 8; blk++) {
        __half2 accA[4], accB[4];
#pragma unroll
        for (int pr = 0; pr < 4; pr++) {
            accA[pr] = __floats2half2_rn(0.f, 0.f);
            accB[pr] = __floats2half2_rn(0.f, 0.f);
        }
#pragma unroll
        for (int it = 0; it < 8; it++) {
            float4 kva = kp[0];
            float4 kvb = kp[32];
            kp += 64;
            u64 kax = pk2(kva.x, kva.x), kay = pk2(kva.y, kva.y);
            u64 kaz = pk2(kva.z, kva.z), kaw = pk2(kva.w, kva.w);
            u64 kbx = pk2(kvb.x, kvb.x), kby = pk2(kvb.y, kvb.y);
            u64 kbz = pk2(kvb.z, kvb.z), kbw = pk2(kvb.w, kvb.w);
#pragma unroll
            for (int pr = 0; pr < 4; pr++) {
                u64 sa = pk2(pA[2 * pr], pA[2 * pr + 1]);
                sa = fma2(qp[pr][0], kax, sa);
                sa = fma2(qp[pr][1], kay, sa);
                sa = fma2(qp[pr][2], kaz, sa);
                sa = fma2(qp[pr][3], kaw, sa);
                float x0, x1; upk2(sa, x0, x1);
                accA[pr] = __hadd2(accA[pr], h2ex2(__floats2half2_rn(x0, x1)));
                u64 sb2 = pk2(pB[2 * pr], pB[2 * pr + 1]);
                sb2 = fma2(qp[pr][0], kbx, sb2);
                sb2 = fma2(qp[pr][1], kby, sb2);
                sb2 = fma2(qp[pr][2], kbz, sb2);
                sb2 = fma2(qp[pr][3], kbw, sb2);
                float y0, y1; upk2(sb2, y0, y1);
                accB[pr] = __hadd2(accB[pr], h2ex2(__floats2half2_rn(y0, y1)));
            }
            pA -= PPITCH; pB -= PPITCH;
        }
#pragma unroll
        for (int pr = 0; pr < 4; pr++) {
            l[2 * pr]     += __low2float(accA[pr])  + __low2float(accB[pr]);
            l[2 * pr + 1] += __high2float(accA[pr]) + __high2float(accB[pr]);
        }
    }

#pragma unroll
    for (int u = 0; u < 8; u++) {
#pragma unroll
        for (int off = 16; off > 0; off >>= 1)
            l[u] += __shfl_xor_sync(0xffffffffu, l[u], off);
    }
    if (lane == 0) {
#pragma unroll
        for (int u = 0; u < 8; u++) {
            int t = qbase + u;
            float4 kv = s4K[t];
            float s = sP[64 * PPITCH];   // diagonal pos bias = scaled R[h,0,0]
            s = fmaf(qv[u][0], kv.x, s);
            s = fmaf(qv[u][1], kv.y, s);
            s = fmaf(qv[u][2], kv.z, s);
            s = fmaf(qv[u][3], kv.w, s);
            float w = __fdividef(ex2(s), l[u]);
            float4 vv = *(const float4*)(g_v + (bh * TOK + t) * 4);
            *(float4*)(g_a + (bh * TOK + t) * 4) =
                make_float4(w * vv.x, w * vv.y, w * vv.z, w * vv.w);
        }
    }
}

// ---------------- Stage 3: Wo proj + residual, then MLP1 (8->32) + gelu ----------------
// 16 threads per token (2 of 32 mlp1 outputs each). grid=512x256.
__global__ void __launch_bounds__(256) k_post1(const float* __restrict__ Wo,
                                               const float* __restrict__ W1,
                                               const float* __restrict__ b1) {
    __shared__ float sWo[64];
    __shared__ float sW1[256];
    __shared__ float sb1[32];
    if (threadIdx.x < 64) sWo[threadIdx.x] = Wo[threadIdx.x];
    sW1[threadIdx.x] = W1[threadIdx.x];
    if (threadIdx.x < 32) sb1[threadIdx.x] = b1[threadIdx.x];
    __syncthreads();
    int gtid = blockIdx.x * 256 + threadIdx.x;
    int p = gtid >> 4, sub = gtid & 15;
    int b = p >> 12, t = p & 4095;
    float vec[8];
#pragma unroll
    for (int h = 0; h < 2; h++) {
        float4 av = *(const float4*)(g_a + (((b << 1) | h) * TOK + t) * 4);
        vec[h * 4 + 0] = av.x; vec[h * 4 + 1] = av.y;
        vec[h * 4 + 2] = av.z; vec[h * 4 + 3] = av.w;
    }
    float acc[8];
    float4 x1a = *(const float4*)(g_x1 + p * 8);
    float4 x1b = *(const float4*)(g_x1 + p * 8 + 4);
    acc[0] = x1a.x; acc[1] = x1a.y; acc[2] = x1a.z; acc[3] = x1a.w;
    acc[4] = x1b.x; acc[5] = x1b.y; acc[6] = x1b.z; acc[7] = x1b.w;
#pragma unroll
    for (int e = 0; e < 8; e++)
#pragma unroll
        for (int c = 0; c < 8; c++) acc[c] = fmaf(vec[e], sWo[e * 8 + c], acc[c]);
    if (sub == 0) {
        *(float4*)(g_x2 + p * 8)     = make_float4(acc[0], acc[1], acc[2], acc[3]);
        *(float4*)(g_x2 + p * 8 + 4) = make_float4(acc[4], acc[5], acc[6], acc[7]);
    }
    float y[8];
#pragma unroll
    for (int c = 0; c < 8; c++) y[c] = acc[c] * 0.57735026918962576f;
    int e0 = sub * 2;
    float o0 = sb1[e0], o1 = sb1[e0 + 1];
#pragma unroll
    for (int c = 0; c < 8; c++) {
        o0 = fmaf(y[c], sW1[c * 32 + e0], o0);
        o1 = fmaf(y[c], sW1[c * 32 + e0 + 1], o1);
    }
    *(float2*)(g_t1 + p * 32 + e0) = make_float2(gelu_f(o0), gelu_f(o1));
}

// ---------------- Stage 4: fused depthwise conv + gelu + MLP3 + residual -> out ----------------
// 8 threads/token: each computes 4 t2 channels (dw conv + gelu) into SMEM, then
// 1 output channel of the 32->8 projection + residual. grid=256x256.
__global__ void __launch_bounds__(256) k_mlp23(const float* __restrict__ W2,
                                               const float* __restrict__ b2,
                                               const float* __restrict__ W3,
                                               const float* __restrict__ b3,
                                               float* __restrict__ out) {
    __shared__ float sW2[288];
    __shared__ float sb2[32];
    __shared__ float sW3[256];   // [e][c]
    __shared__ float sb3[8];
    __shared__ float st2[32 * 36];   // 32 tokens x 32ch, pitch 36
    sW3[threadIdx.x] = W3[threadIdx.x];
    if (threadIdx.x < 288 - 256) sW2[256 + threadIdx.x] = W2[256 + threadIdx.x];
    sW2[threadIdx.x] = W2[threadIdx.x];
    if (threadIdx.x < 32) sb2[threadIdx.x] = b2[threadIdx.x];
    if (threadIdx.x < 8) sb3[threadIdx.x] = b3[threadIdx.x];
    __syncthreads();
    int gtid = blockIdx.x * 256 + threadIdx.x;
    int p = gtid >> 3, sub = gtid & 7, e0 = sub * 4;
    int tl = threadIdx.x >> 3;   // local token 0..31
    int b = p >> 12, rem = p & 4095, i = rem >> 6, j = rem & 63;
    float acc[4];
#pragma unroll
    for (int ee = 0; ee < 4; ee++) acc[ee] = sb2[e0 + ee];
#pragma unroll
    for (int di = 0; di < 3; di++) {
        int row = (i + di + 63) & 63;
#pragma unroll
        for (int dj = 0; dj < 3; dj++) {
            int col = (j + dj + 63) & 63;
            float4 tv = *(const float4*)(g_t1 + ((((b << 12) | (row << 6)) | col) * 32 + e0));
            const float* wp = sW2 + (di * 3 + dj) * 32 + e0;
            acc[0] = fmaf(tv.x, wp[0], acc[0]);
            acc[1] = fmaf(tv.y, wp[1], acc[1]);
            acc[2] = fmaf(tv.z, wp[2], acc[2]);
            acc[3] = fmaf(tv.w, wp[3], acc[3]);
        }
    }
    float4 o;
    o.x = gelu_f(acc[0]); o.y = gelu_f(acc[1]);
    o.z = gelu_f(acc[2]); o.w = gelu_f(acc[3]);
    *(float4*)(st2 + tl * 36 + e0) = o;
    __syncthreads();
    int c = sub;
    float a = sb3[c] + g_x2[p * 8 + c];
    const float* t2p = st2 + tl * 36;
#pragma unroll
    for (int q4 = 0; q4 < 8; q4++) {
        float4 tv = *(const float4*)(t2p + q4 * 4);
        int e = q4 * 4;
        a = fmaf(tv.x, sW3[(e + 0) * 8 + c], a);
        a = fmaf(tv.y, sW3[(e + 1) * 8 + c], a);
        a = fmaf(tv.z, sW3[(e + 2) * 8 + c], a);
        a = fmaf(tv.w, sW3[(e + 3) * 8 + c], a);
    }
    out[p * 8 + c] = a;
}

extern "C" void kernel_launch(void* const* d_in, const int* in_sizes, int n_in,
                              void* d_out, int out_size) {
    const float* x      = (const float*)d_in[0];
    const float* conv_W = (const float*)d_in[1];
    const float* conv_b = (const float*)d_in[2];
    const float* Wq     = (const float*)d_in[3];
    const float* Wk     = (const float*)d_in[4];
    const float* Wv     = (const float*)d_in[5];
    const float* pos    = (const float*)d_in[6];
    const float* Wo     = (const float*)d_in[7];
    const float* m1W    = (const float*)d_in[8];
    const float* m1b    = (const float*)d_in[9];
    const float* m2W    = (const float*)d_in[10];
    const float* m2b    = (const float*)d_in[11];
    const float* m3W    = (const float*)d_in[12];
    const float* m3b    = (const float*)d_in[13];
    float* out = (float*)d_out;

    const int ATTN_SMEM = (16384 + 128 * PPITCH) * 4;   // 102400 bytes
    cudaFuncSetAttribute(k_attn, cudaFuncAttributeMaxDynamicSharedMemorySize, ATTN_SMEM);

    k_gelu<<<256, 256>>>(x);
    k_conv_qkv<<<256, 128>>>(x, conv_W, conv_b, Wq, Wk, Wv);
    dim3 ag(64, 4);
    k_attn<<<ag, 256, ATTN_SMEM>>>(pos);
    k_post1<<<512, 256>>>(Wo, m1W, m1b);
    k_mlp23<<<256, 256>>>(m2W, m2b, m3W, m3b, out);
}

// round 7
// speedup vs baseline: 3.3005x; 1.1515x over previous
#include <cuda_runtime.h>
#include <cuda_fp16.h>
#include <math.h>

// Problem constants: B=2, M=N=64, H=2, C=8, D=4
#define TOK  4096
#define TOT  8192

#define SCALE_LOG2E 0.72134752044448170f   // 0.5 * log2(e)
#define PP2 70                              // pos half2 row pitch (64 + 6)

// Scratch (allocation-free: __device__ globals)
__device__ float g_x1[65536];
__device__ float g_q[65536];       // [bh][t][d], pre-scaled by 0.5*log2e
__device__ float g_k[65536];
__device__ float g_v[65536];
__device__ float g_a[65536];
__device__ float g_x2[65536];
__device__ float g_t1[262144];

__device__ __forceinline__ float gelu_f(float x) {
    float z2 = 1.5957691216057308f * fmaf(0.044715f, x * x * x, x);  // 2z
    return __fdividef(x, 1.0f + __expf(-z2));
}
__device__ __forceinline__ float ex2(float x) {
    float r; asm("ex2.approx.ftz.f32 %0, %1;" : "=f"(r) : "f"(x)); return r;
}
__device__ __forceinline__ __half2 h2ex2(__half2 x) {
    __half2 r;
    asm("ex2.approx.f16x2 %0, %1;"
        : "=r"(*reinterpret_cast<unsigned*>(&r))
        : "r"(*reinterpret_cast<const unsigned*>(&x)));
    return r;
}

// ---------------- Stage 1: gelu + circular conv (8->8) + residual + QKV ----------------
// 8x8 token tile per block with 10x10 halo gelu'd into SMEM. 4 threads/token. grid=128x256.
__global__ void __launch_bounds__(256) k_conv_qkv(
        const float* __restrict__ x, const float* __restrict__ W,
        const float* __restrict__ bias, const float* __restrict__ Wq,
        const float* __restrict__ Wk, const float* __restrict__ Wv) {
    __shared__ float sW[576];
    __shared__ float sb[8];
    __shared__ float sQKV[192];
    __shared__ float sX[10 * 10 * 8];   // halo'd gelu tile
    for (int i = threadIdx.x; i < 576; i += 256) sW[i] = W[i];
    if (threadIdx.x < 8) sb[threadIdx.x] = bias[threadIdx.x];
    if (threadIdx.x < 64) {
        sQKV[threadIdx.x]       = Wq[threadIdx.x];
        sQKV[64 + threadIdx.x]  = Wk[threadIdx.x];
        sQKV[128 + threadIdx.x] = Wv[threadIdx.x];
    }
    int b = blockIdx.x >> 6;
    int tile = blockIdx.x & 63;
    int ti = tile >> 3, tj = tile & 7;
    // fill halo tile: 100 positions x 2 float4
    for (int u = threadIdx.x; u < 200; u += 256) {
        int pos = u >> 1, hf = u & 1;
        int pi = pos / 10, pj = pos - pi * 10;
        int row = (ti * 8 + pi - 1) & 63;
        int col = (tj * 8 + pj - 1) & 63;
        float4 xv = *(const float4*)(x + ((((b << 12) | (row << 6)) | col) << 3) + hf * 4);
        float4 g;
        g.x = gelu_f(xv.x); g.y = gelu_f(xv.y); g.z = gelu_f(xv.z); g.w = gelu_f(xv.w);
        *(float4*)(sX + pos * 8 + hf * 4) = g;
    }
    __syncthreads();

    int tl = threadIdx.x >> 2, quarter = threadIdx.x & 3;
    int cin0 = quarter * 2;
    int li = tl >> 3, lj = tl & 7;
    int p = (b << 12) | ((ti * 8 + li) << 6) | (tj * 8 + lj);
    float acc[8];
    if (quarter == 0) {
#pragma unroll
        for (int c = 0; c < 8; c++) acc[c] = sb[c] + x[p * 8 + c];
    } else {
#pragma unroll
        for (int c = 0; c < 8; c++) acc[c] = 0.f;
    }
#pragma unroll
    for (int di = 0; di < 3; di++) {
#pragma unroll
        for (int dj = 0; dj < 3; dj++) {
            float2 xv2 = *(const float2*)(sX + ((li + di) * 10 + (lj + dj)) * 8 + cin0);
            const float* wp = sW + (di * 3 + dj) * 64 + cin0 * 8;
#pragma unroll
            for (int c = 0; c < 8; c++) acc[c] = fmaf(xv2.x, wp[c], acc[c]);
#pragma unroll
            for (int c = 0; c < 8; c++) acc[c] = fmaf(xv2.y, wp[8 + c], acc[c]);
        }
    }
#pragma unroll
    for (int c = 0; c < 8; c++) acc[c] += __shfl_xor_sync(0xffffffffu, acc[c], 1);
#pragma unroll
    for (int c = 0; c < 8; c++) acc[c] += __shfl_xor_sync(0xffffffffu, acc[c], 2);

    int t = p & 4095;
    if (quarter == 0) {
        *(float4*)(g_x1 + p * 8)     = make_float4(acc[0], acc[1], acc[2], acc[3]);
        *(float4*)(g_x1 + p * 8 + 4) = make_float4(acc[4], acc[5], acc[6], acc[7]);
    } else {
        float y[8];
#pragma unroll
        for (int c = 0; c < 8; c++) y[c] = acc[c] * 0.70710678118654752f;
        const float* wsel = sQKV + (quarter - 1) * 64;
        float scale = (quarter == 1) ? SCALE_LOG2E : 1.0f;
        float* gdst = (quarter == 1) ? g_q : (quarter == 2) ? g_k : g_v;
#pragma unroll
        for (int h = 0; h < 2; h++) {
            float o4[4];
#pragma unroll
            for (int d = 0; d < 4; d++) {
                int e = h * 4 + d;
                float v = 0.f;
#pragma unroll
                for (int c = 0; c < 8; c++) v = fmaf(y[c], wsel[c * 8 + e], v);
                o4[d] = v * scale;
            }
            *(float4*)(gdst + ((((b << 1) | h) * TOK + t) << 2)) =
                make_float4(o4[0], o4[1], o4[2], o4[3]);
        }
    }
}

// ---------------- Stage 2: attention (DIAGONAL: a_n = attn[n,n] * v_n) ----------------
// Full half2 pipeline: K as half2 pairs, pos as pre-paired half2 table, HFMA2 scores,
// f16x2 EX2, f16 partial sums (8 terms) flushed to f32. 8 warps x 8 queries, 2 CTAs/SM.
// smem layout (float slots): sK2[8192] | sP2[128*PP2] | sPf[4096]
__global__ void __launch_bounds__(256, 2) k_attn(const float* __restrict__ pos) {
    extern __shared__ float smem[];
    __half2* sK2 = (__half2*)smem;                     // 4096 keys x 2 half2
    __half2* sP2 = (__half2*)(smem + 8192);            // 128 x PP2
    float*   sPf = smem + 8192 + 128 * PP2;            // staging, f32 scaled pos
    int bh = blockIdx.y;
    int h = bh & 1;
    const float* gP = pos + h * 4096;
    for (int i = threadIdx.x; i < 4096; i += 256) sPf[i] = gP[i] * SCALE_LOG2E;
    const float4* gK = (const float4*)(g_k + bh * (TOK * 4));
    for (int i = threadIdx.x; i < 4096; i += 256) {
        float4 kv = gK[i];
        sK2[i * 2]     = __floats2half2_rn(kv.x, kv.y);
        sK2[i * 2 + 1] = __floats2half2_rn(kv.z, kv.w);
    }
    __syncthreads();
    for (int i = threadIdx.x; i < 128 * PP2; i += 256) {
        int r = i / PP2, c = i - r * PP2;
        int row = (r & 63) << 6;
        sP2[i] = __floats2half2_rn(sPf[row + (c & 63)], sPf[row + ((c + 1) & 63)]);
    }
    __syncthreads();

    int warp = threadIdx.x >> 5, lane = threadIdx.x & 31;
    int mi = blockIdx.x;
    int nbase = warp * 8;
    int qbase = (mi << 6) | nbase;

    float qv[8][4];
#pragma unroll
    for (int u = 0; u < 8; u++) {
        float4 qq = *(const float4*)(g_q + (bh * TOK + qbase + u) * 4);
        qv[u][0] = qq.x; qv[u][1] = qq.y; qv[u][2] = qq.z; qv[u][3] = qq.w;
    }
    __half2 qh[4][4];
#pragma unroll
    for (int pr = 0; pr < 4; pr++)
#pragma unroll
        for (int d = 0; d < 4; d++)
            qh[pr][d] = __floats2half2_rn(qv[2 * pr][d], qv[2 * pr + 1][d]);

    int pc0a = (nbase - lane) & 63;
    int pc0b = (nbase - lane - 32) & 63;
    const __half2* pA = sP2 + (mi + 64) * PP2 + pc0a;
    const __half2* pB = sP2 + (mi + 64) * PP2 + pc0b;
    const uint2* kp = (const uint2*)sK2 + lane;

    float l[8];
#pragma unroll
    for (int u = 0; u < 8; u++) l[u] = 0.f;

#pragma unroll 1
    for (int blk = 0; blk < 8; blk++) {
        __half2 accA[4], accB[4];
#pragma unroll
        for (int pr = 0; pr < 4; pr++) {
            accA[pr] = __floats2half2_rn(0.f, 0.f);
            accB[pr] = __floats2half2_rn(0.f, 0.f);
        }
#pragma unroll
        for (int it = 0; it < 8; it++) {
            uint2 ka = kp[0];
            uint2 kb = kp[32];
            kp += 64;
            __half2 ka01 = *reinterpret_cast<__half2*>(&ka.x);
            __half2 ka23 = *reinterpret_cast<__half2*>(&ka.y);
            __half2 kb01 = *reinterpret_cast<__half2*>(&kb.x);
            __half2 kb23 = *reinterpret_cast<__half2*>(&kb.y);
            __half2 a0 = __low2half2(ka01), a1 = __high2half2(ka01);
            __half2 a2 = __low2half2(ka23), a3 = __high2half2(ka23);
            __half2 b0 = __low2half2(kb01), b1 = __high2half2(kb01);
            __half2 b2 = __low2half2(kb23), b3 = __high2half2(kb23);
#pragma unroll
            for (int pr = 0; pr < 4; pr++) {
                __half2 s = pA[2 * pr];
                s = __hfma2(qh[pr][0], a0, s);
                s = __hfma2(qh[pr][1], a1, s);
                s = __hfma2(qh[pr][2], a2, s);
                s = __hfma2(qh[pr][3], a3, s);
                accA[pr] = __hadd2(accA[pr], h2ex2(s));
                __half2 t2 = pB[2 * pr];
                t2 = __hfma2(qh[pr][0], b0, t2);
                t2 = __hfma2(qh[pr][1], b1, t2);
                t2 = __hfma2(qh[pr][2], b2, t2);
                t2 = __hfma2(qh[pr][3], b3, t2);
                accB[pr] = __hadd2(accB[pr], h2ex2(t2));
            }
            pA -= PP2; pB -= PP2;
        }
#pragma unroll
        for (int pr = 0; pr < 4; pr++) {
            l[2 * pr]     += __low2float(accA[pr])  + __low2float(accB[pr]);
            l[2 * pr + 1] += __high2float(accA[pr]) + __high2float(accB[pr]);
        }
    }

#pragma unroll
    for (int u = 0; u < 8; u++) {
#pragma unroll
        for (int off = 16; off > 0; off >>= 1)
            l[u] += __shfl_xor_sync(0xffffffffu, l[u], off);
    }
    if (lane == 0) {
        float pdiag = gP[0] * SCALE_LOG2E;
#pragma unroll
        for (int u = 0; u < 8; u++) {
            int t = qbase + u;
            float4 kv = *(const float4*)(g_k + (bh * TOK + t) * 4);
            float s = pdiag;
            s = fmaf(qv[u][0], kv.x, s);
            s = fmaf(qv[u][1], kv.y, s);
            s = fmaf(qv[u][2], kv.z, s);
            s = fmaf(qv[u][3], kv.w, s);
            float w = __fdividef(ex2(s), l[u]);
            float4 vv = *(const float4*)(g_v + (bh * TOK + t) * 4);
            *(float4*)(g_a + (bh * TOK + t) * 4) =
                make_float4(w * vv.x, w * vv.y, w * vv.z, w * vv.w);
        }
    }
}

// ---------------- Stage 3: Wo proj + residual, then MLP1 (8->32) + gelu ----------------
// 8 threads/token, shfl.idx allgather, no redundant projection. grid=256x256.
__global__ void __launch_bounds__(256) k_post1(const float* __restrict__ Wo,
                                               const float* __restrict__ W1,
                                               const float* __restrict__ b1) {
    __shared__ float sWo[64];
    __shared__ float sW1[256];
    __shared__ float sb1[32];
    if (threadIdx.x < 64) sWo[threadIdx.x] = Wo[threadIdx.x];
    sW1[threadIdx.x] = W1[threadIdx.x];
    if (threadIdx.x < 32) sb1[threadIdx.x] = b1[threadIdx.x];
    __syncthreads();
    int gtid = blockIdx.x * 256 + threadIdx.x;
    int p = gtid >> 3, c = gtid & 7;
    int b = p >> 12, t = p & 4095;
    int hh = c >> 2, d = c & 3;
    float av = g_a[((((b << 1) | hh) * TOK + t) << 2) + d];
    int base = threadIdx.x & ~7;
    float vec[8];
#pragma unroll
    for (int k = 0; k < 8; k++)
        vec[k] = __shfl_sync(0xffffffffu, av, base | k);
    float x2c = g_x1[gtid];
#pragma unroll
    for (int e = 0; e < 8; e++) x2c = fmaf(vec[e], sWo[e * 8 + c], x2c);
    g_x2[gtid] = x2c;
    float y[8];
#pragma unroll
    for (int k = 0; k < 8; k++)
        y[k] = __shfl_sync(0xffffffffu, x2c, base | k) * 0.57735026918962576f;
    int e0 = c * 4;
    float o[4];
#pragma unroll
    for (int ee = 0; ee < 4; ee++) {
        int e = e0 + ee;
        float v = sb1[e];
#pragma unroll
        for (int cc = 0; cc < 8; cc++) v = fmaf(y[cc], sW1[cc * 32 + e], v);
        o[ee] = gelu_f(v);
    }
    *(float4*)(g_t1 + p * 32 + e0) = make_float4(o[0], o[1], o[2], o[3]);
}

// ---------------- Stage 4: fused depthwise conv + gelu + MLP3 + residual -> out ----------------
__global__ void __launch_bounds__(256) k_mlp23(const float* __restrict__ W2,
                                               const float* __restrict__ b2,
                                               const float* __restrict__ W3,
                                               const float* __restrict__ b3,
                                               float* __restrict__ out) {
    __shared__ float sW2[288];
    __shared__ float sb2[32];
    __shared__ float sW3[256];   // [e][c]
    __shared__ float sb3[8];
    __shared__ float st2[32 * 36];
    sW3[threadIdx.x] = W3[threadIdx.x];
    if (threadIdx.x < 288 - 256) sW2[256 + threadIdx.x] = W2[256 + threadIdx.x];
    sW2[threadIdx.x] = W2[threadIdx.x];
    if (threadIdx.x < 32) sb2[threadIdx.x] = b2[threadIdx.x];
    if (threadIdx.x < 8) sb3[threadIdx.x] = b3[threadIdx.x];
    __syncthreads();
    int gtid = blockIdx.x * 256 + threadIdx.x;
    int p = gtid >> 3, sub = gtid & 7, e0 = sub * 4;
    int tl = threadIdx.x >> 3;
    int b = p >> 12, rem = p & 4095, i = rem >> 6, j = rem & 63;
    float acc[4];
#pragma unroll
    for (int ee = 0; ee < 4; ee++) acc[ee] = sb2[e0 + ee];
#pragma unroll
    for (int di = 0; di < 3; di++) {
        int row = (i + di + 63) & 63;
#pragma unroll
        for (int dj = 0; dj < 3; dj++) {
            int col = (j + dj + 63) & 63;
            float4 tv = *(const float4*)(g_t1 + ((((b << 12) | (row << 6)) | col) * 32 + e0));
            const float* wp = sW2 + (di * 3 + dj) * 32 + e0;
            acc[0] = fmaf(tv.x, wp[0], acc[0]);
            acc[1] = fmaf(tv.y, wp[1], acc[1]);
            acc[2] = fmaf(tv.z, wp[2], acc[2]);
            acc[3] = fmaf(tv.w, wp[3], acc[3]);
        }
    }
    float4 o;
    o.x = gelu_f(acc[0]); o.y = gelu_f(acc[1]);
    o.z = gelu_f(acc[2]); o.w = gelu_f(acc[3]);
    *(float4*)(st2 + tl * 36 + e0) = o;
    __syncthreads();
    int c = sub;
    float a = sb3[c] + g_x2[p * 8 + c];
    const float* t2p = st2 + tl * 36;
#pragma unroll
    for (int q4 = 0; q4 < 8; q4++) {
        float4 tv = *(const float4*)(t2p + q4 * 4);
        int e = q4 * 4;
        a = fmaf(tv.x, sW3[(e + 0) * 8 + c], a);
        a = fmaf(tv.y, sW3[(e + 1) * 8 + c], a);
        a = fmaf(tv.z, sW3[(e + 2) * 8 + c], a);
        a = fmaf(tv.w, sW3[(e + 3) * 8 + c], a);
    }
    out[p * 8 + c] = a;
}

extern "C" void kernel_launch(void* const* d_in, const int* in_sizes, int n_in,
                              void* d_out, int out_size) {
    const float* x      = (const float*)d_in[0];
    const float* conv_W = (const float*)d_in[1];
    const float* conv_b = (const float*)d_in[2];
    const float* Wq     = (const float*)d_in[3];
    const float* Wk     = (const float*)d_in[4];
    const float* Wv     = (const float*)d_in[5];
    const float* pos    = (const float*)d_in[6];
    const float* Wo     = (const float*)d_in[7];
    const float* m1W    = (const float*)d_in[8];
    const float* m1b    = (const float*)d_in[9];
    const float* m2W    = (const float*)d_in[10];
    const float* m2b    = (const float*)d_in[11];
    const float* m3W    = (const float*)d_in[12];
    const float* m3b    = (const float*)d_in[13];
    float* out = (float*)d_out;

    const int ATTN_SMEM = (8192 + 128 * PP2 + 4096) * 4;   // 85 KB
    cudaFuncSetAttribute(k_attn, cudaFuncAttributeMaxDynamicSharedMemorySize, ATTN_SMEM);

    k_conv_qkv<<<128, 256>>>(x, conv_W, conv_b, Wq, Wk, Wv);
    dim3 ag(64, 4);
    k_attn<<<ag, 256, ATTN_SMEM>>>(pos);
    k_post1<<<256, 256>>>(Wo, m1W, m1b);
    k_mlp23<<<256, 256>>>(m2W, m2b, m3W, m3b, out);
}

// round 8
// speedup vs baseline: 3.7103x; 1.1242x over previous
#include <cuda_runtime.h>
#include <cuda_fp16.h>
#include <math.h>

// Problem constants: B=2, M=N=64, H=2, C=8, D=4
#define TOK  4096
#define TOT  8192

#define SCALE_LOG2E 0.72134752044448170f   // 0.5 * log2(e)
#define PP2 70                              // pos half2 row pitch

// Scratch (allocation-free: __device__ globals)
__device__ float g_x1[65536];
__device__ float g_q[65536];       // [bh][t][d], pre-scaled by 0.5*log2e
__device__ float g_k[65536];
__device__ float g_v[65536];
__device__ float g_a[65536];

__device__ __forceinline__ float gelu_f(float x) {
    float z2 = 1.5957691216057308f * fmaf(0.044715f, x * x * x, x);  // 2z
    return __fdividef(x, 1.0f + __expf(-z2));
}
__device__ __forceinline__ float ex2(float x) {
    float r; asm("ex2.approx.ftz.f32 %0, %1;" : "=f"(r) : "f"(x)); return r;
}
__device__ __forceinline__ __half2 h2ex2(__half2 x) {
    __half2 r;
    asm("ex2.approx.f16x2 %0, %1;"
        : "=r"(*reinterpret_cast<unsigned*>(&r))
        : "r"(*reinterpret_cast<const unsigned*>(&x)));
    return r;
}

// ---------------- Stage 1: gelu + circular conv (8->8) + residual + QKV ----------------
// 4x8 token tile, 8 threads/token (1 input channel each), 3 shfl-reduce rounds. grid=256.
__global__ void __launch_bounds__(256) k_conv_qkv(
        const float* __restrict__ x, const float* __restrict__ W,
        const float* __restrict__ bias, const float* __restrict__ Wq,
        const float* __restrict__ Wk, const float* __restrict__ Wv) {
    __shared__ float sW[576];
    __shared__ float sb[8];
    __shared__ float sQKV[192];
    __shared__ float sX[60 * 8];   // 6x10 halo gelu tile
    for (int i = threadIdx.x; i < 576; i += 256) sW[i] = W[i];
    if (threadIdx.x < 8) sb[threadIdx.x] = bias[threadIdx.x];
    if (threadIdx.x < 64) {
        sQKV[threadIdx.x]       = Wq[threadIdx.x];
        sQKV[64 + threadIdx.x]  = Wk[threadIdx.x];
        sQKV[128 + threadIdx.x] = Wv[threadIdx.x];
    }
    int b = blockIdx.x >> 7;
    int tile = blockIdx.x & 127;
    int ti = tile >> 3, tj = tile & 7;
    // gelu the 6x10 halo (480 channel-cells)
    for (int u = threadIdx.x; u < 480; u += 256) {
        int cell = u >> 3, ch = u & 7;
        int pi = cell / 10, pj = cell - pi * 10;
        int row = (ti * 4 + pi - 1) & 63;
        int col = (tj * 8 + pj - 1) & 63;
        sX[u] = gelu_f(x[((((b << 12) | (row << 6)) | col) << 3) + ch]);
    }
    __syncthreads();

    int tl = threadIdx.x >> 3, cin = threadIdx.x & 7;
    int li = tl >> 3, lj = tl & 7;
    int p = (b << 12) | ((ti * 4 + li) << 6) | (tj * 8 + lj);
    float acc[8];
#pragma unroll
    for (int c = 0; c < 8; c++) acc[c] = 0.f;
#pragma unroll
    for (int di = 0; di < 3; di++) {
#pragma unroll
        for (int dj = 0; dj < 3; dj++) {
            float xv = sX[((li + di) * 10 + (lj + dj)) * 8 + cin];
            const float* wp = sW + (di * 3 + dj) * 64 + cin * 8;
#pragma unroll
            for (int c = 0; c < 8; c++) acc[c] = fmaf(xv, wp[c], acc[c]);
        }
    }
    if (cin == 0) {   // fold bias + residual once
        float4 xa = *(const float4*)(x + p * 8);
        float4 xb = *(const float4*)(x + p * 8 + 4);
        acc[0] += sb[0] + xa.x; acc[1] += sb[1] + xa.y;
        acc[2] += sb[2] + xa.z; acc[3] += sb[3] + xa.w;
        acc[4] += sb[4] + xb.x; acc[5] += sb[5] + xb.y;
        acc[6] += sb[6] + xb.z; acc[7] += sb[7] + xb.w;
    }
#pragma unroll
    for (int c = 0; c < 8; c++) acc[c] += __shfl_xor_sync(0xffffffffu, acc[c], 1);
#pragma unroll
    for (int c = 0; c < 8; c++) acc[c] += __shfl_xor_sync(0xffffffffu, acc[c], 2);
#pragma unroll
    for (int c = 0; c < 8; c++) acc[c] += __shfl_xor_sync(0xffffffffu, acc[c], 4);

    int t = p & 4095;
    int e = cin;
    g_x1[p * 8 + e] = acc[e];
    float y[8];
#pragma unroll
    for (int c = 0; c < 8; c++) y[c] = acc[c] * 0.70710678118654752f;
    float qe = 0.f, ke = 0.f, ve = 0.f;
#pragma unroll
    for (int c = 0; c < 8; c++) {
        qe = fmaf(y[c], sQKV[c * 8 + e], qe);
        ke = fmaf(y[c], sQKV[64 + c * 8 + e], ke);
        ve = fmaf(y[c], sQKV[128 + c * 8 + e], ve);
    }
    int h = e >> 2, d = e & 3;
    int idx = ((((b << 1) | h) * TOK + t) << 2) + d;
    g_q[idx] = qe * SCALE_LOG2E;
    g_k[idx] = ke;
    g_v[idx] = ve;
}

// ---------------- Stage 2: attention (DIAGONAL: a_n = attn[n,n] * v_n) ----------------
// Full half2 pipeline. 8 warps x 8 queries; grid=(64, 4), 256 thr.
__global__ void __launch_bounds__(256, 2) k_attn(const float* __restrict__ pos) {
    extern __shared__ float smem[];
    __half2* sK2 = (__half2*)smem;                     // 4096 keys x 2 half2
    __half2* sP2 = (__half2*)(smem + 8192);            // 128 x PP2 (rows doubled)
    int bh = blockIdx.y;
    int h = bh & 1;
    const float* gP = pos + h * 4096;
    const float4* gK = (const float4*)(g_k + bh * (TOK * 4));
    for (int i = threadIdx.x; i < 4096; i += 256) {
        float4 kv = gK[i];
        sK2[i * 2]     = __floats2half2_rn(kv.x, kv.y);
        sK2[i * 2 + 1] = __floats2half2_rn(kv.z, kv.w);
    }
    for (int i = threadIdx.x; i < 128 * PP2; i += 256) {
        int r = i / PP2, c = i - r * PP2;
        int row = (r & 63) << 6;
        sP2[i] = __floats2half2_rn(gP[row + (c & 63)] * SCALE_LOG2E,
                                   gP[row + ((c + 1) & 63)] * SCALE_LOG2E);
    }
    __syncthreads();

    int warp = threadIdx.x >> 5, lane = threadIdx.x & 31;
    int mi = blockIdx.x;
    int nbase = warp * 8;
    int qbase = (mi << 6) | nbase;

    float qv[8][4];
#pragma unroll
    for (int u = 0; u < 8; u++) {
        float4 qq = *(const float4*)(g_q + (bh * TOK + qbase + u) * 4);
        qv[u][0] = qq.x; qv[u][1] = qq.y; qv[u][2] = qq.z; qv[u][3] = qq.w;
    }
    __half2 qh[4][4];
#pragma unroll
    for (int pr = 0; pr < 4; pr++)
#pragma unroll
        for (int d = 0; d < 4; d++)
            qh[pr][d] = __floats2half2_rn(qv[2 * pr][d], qv[2 * pr + 1][d]);

    int pc0a = (nbase - lane) & 63;
    int pc0b = (nbase - lane - 32) & 63;
    const __half2* pA = sP2 + (mi + 64) * PP2 + pc0a;
    const __half2* pB = sP2 + (mi + 64) * PP2 + pc0b;
    const uint2* kp = (const uint2*)sK2 + lane;

    float l[8];
#pragma unroll
    for (int u = 0; u < 8; u++) l[u] = 0.f;

#pragma unroll 1
    for (int blk = 0; blk < 8; blk++) {
        __half2 accA[4], accB[4];
#pragma unroll
        for (int pr = 0; pr < 4; pr++) {
            accA[pr] = __floats2half2_rn(0.f, 0.f);
            accB[pr] = __floats2half2_rn(0.f, 0.f);
        }
#pragma unroll
        for (int it = 0; it < 8; it++) {
            uint2 ka = kp[0];
            uint2 kb = kp[32];
            kp += 64;
            __half2 ka01 = *reinterpret_cast<__half2*>(&ka.x);
            __half2 ka23 = *reinterpret_cast<__half2*>(&ka.y);
            __half2 kb01 = *reinterpret_cast<__half2*>(&kb.x);
            __half2 kb23 = *reinterpret_cast<__half2*>(&kb.y);
            __half2 a0 = __low2half2(ka01), a1 = __high2half2(ka01);
            __half2 a2 = __low2half2(ka23), a3 = __high2half2(ka23);
            __half2 b0 = __low2half2(kb01), b1 = __high2half2(kb01);
            __half2 b2 = __low2half2(kb23), b3 = __high2half2(kb23);
#pragma unroll
            for (int pr = 0; pr < 4; pr++) {
                __half2 s = pA[2 * pr];
                s = __hfma2(qh[pr][0], a0, s);
                s = __hfma2(qh[pr][1], a1, s);
                s = __hfma2(qh[pr][2], a2, s);
                s = __hfma2(qh[pr][3], a3, s);
                accA[pr] = __hadd2(accA[pr], h2ex2(s));
                __half2 t2 = pB[2 * pr];
                t2 = __hfma2(qh[pr][0], b0, t2);
                t2 = __hfma2(qh[pr][1], b1, t2);
                t2 = __hfma2(qh[pr][2], b2, t2);
                t2 = __hfma2(qh[pr][3], b3, t2);
                accB[pr] = __hadd2(accB[pr], h2ex2(t2));
            }
            pA -= PP2; pB -= PP2;
        }
#pragma unroll
        for (int pr = 0; pr < 4; pr++) {
            l[2 * pr]     += __low2float(accA[pr])  + __low2float(accB[pr]);
            l[2 * pr + 1] += __high2float(accA[pr]) + __high2float(accB[pr]);
        }
    }

#pragma unroll
    for (int u = 0; u < 8; u++) {
#pragma unroll
        for (int off = 16; off > 0; off >>= 1)
            l[u] += __shfl_xor_sync(0xffffffffu, l[u], off);
    }
    if (lane == 0) {
        float pdiag = gP[0] * SCALE_LOG2E;
#pragma unroll
        for (int u = 0; u < 8; u++) {
            int t = qbase + u;
            float4 kv = *(const float4*)(g_k + (bh * TOK + t) * 4);
            float s = pdiag;
            s = fmaf(qv[u][0], kv.x, s);
            s = fmaf(qv[u][1], kv.y, s);
            s = fmaf(qv[u][2], kv.z, s);
            s = fmaf(qv[u][3], kv.w, s);
            float w = __fdividef(ex2(s), l[u]);
            float4 vv = *(const float4*)(g_v + (bh * TOK + t) * 4);
            *(float4*)(g_a + (bh * TOK + t) * 4) =
                make_float4(w * vv.x, w * vv.y, w * vv.z, w * vv.w);
        }
    }
}

// ---------------- Stage 3: fused tail ----------------
// Wo proj + residual -> x2; MLP1 + gelu -> t1 (halo, in SMEM);
// depthwise conv + gelu -> t2 (SMEM); MLP3 + residual -> out.
// Block = 4x8 interior tile, halo 6x10, 256 threads. grid=256.
__global__ void __launch_bounds__(256) k_tail(
        const float* __restrict__ Wo,
        const float* __restrict__ W1, const float* __restrict__ b1,
        const float* __restrict__ W2, const float* __restrict__ b2,
        const float* __restrict__ W3, const float* __restrict__ b3,
        float* __restrict__ out) {
    __shared__ float sWo[64];
    __shared__ float sW1[256];
    __shared__ float sb1[32];
    __shared__ float sW2[288];
    __shared__ float sb2[32];
    __shared__ float sW3[256];
    __shared__ float sb3[8];
    __shared__ float st1[60 * 36];    // halo t1: 60 tokens x 32ch, pitch 36
    __shared__ float st2[32 * 36];    // interior t2
    __shared__ float sx2[32 * 8];     // interior x2 (residual)
    if (threadIdx.x < 64) sWo[threadIdx.x] = Wo[threadIdx.x];
    sW1[threadIdx.x] = W1[threadIdx.x];
    if (threadIdx.x < 32) sb1[threadIdx.x] = b1[threadIdx.x];
    sW2[threadIdx.x] = W2[threadIdx.x];
    if (threadIdx.x < 32) sW2[256 + threadIdx.x] = W2[256 + threadIdx.x];
    if (threadIdx.x < 32) sb2[threadIdx.x] = b2[threadIdx.x];
    sW3[threadIdx.x] = W3[threadIdx.x];
    if (threadIdx.x < 8) sb3[threadIdx.x] = b3[threadIdx.x];
    __syncthreads();

    int b = blockIdx.x >> 7;
    int tile = blockIdx.x & 127;
    int ti = tile >> 3, tj = tile & 7;

    // Phase 1: Wo proj + residual + MLP1 for 60 halo tokens, 4 threads/token
    if (threadIdx.x < 240) {
        int token = threadIdx.x >> 2, quarter = threadIdx.x & 3;
        int pi = token / 10, pj = token - pi * 10;
        int row = (ti * 4 + pi - 1) & 63;
        int col = (tj * 8 + pj - 1) & 63;
        int p = (b << 12) | (row << 6) | col;
        int t = p & 4095;
        float vec[8];
#pragma unroll
        for (int h = 0; h < 2; h++) {
            float4 av = *(const float4*)(g_a + ((((b << 1) | h) * TOK + t) << 2));
            vec[h * 4 + 0] = av.x; vec[h * 4 + 1] = av.y;
            vec[h * 4 + 2] = av.z; vec[h * 4 + 3] = av.w;
        }
        float acc[8];
        float4 x1a = *(const float4*)(g_x1 + p * 8);
        float4 x1b = *(const float4*)(g_x1 + p * 8 + 4);
        acc[0] = x1a.x; acc[1] = x1a.y; acc[2] = x1a.z; acc[3] = x1a.w;
        acc[4] = x1b.x; acc[5] = x1b.y; acc[6] = x1b.z; acc[7] = x1b.w;
#pragma unroll
        for (int e = 0; e < 8; e++)
#pragma unroll
            for (int c = 0; c < 8; c++) acc[c] = fmaf(vec[e], sWo[e * 8 + c], acc[c]);
        // interior x2 store
        if (quarter == 0 && pi >= 1 && pi <= 4 && pj >= 1 && pj <= 8) {
            int lt = (pi - 1) * 8 + (pj - 1);
            *(float4*)(sx2 + lt * 8)     = make_float4(acc[0], acc[1], acc[2], acc[3]);
            *(float4*)(sx2 + lt * 8 + 4) = make_float4(acc[4], acc[5], acc[6], acc[7]);
        }
        float y[8];
#pragma unroll
        for (int c = 0; c < 8; c++) y[c] = acc[c] * 0.57735026918962576f;
        int e0 = quarter * 8;
        float* dst = st1 + token * 36 + e0;
#pragma unroll
        for (int ee = 0; ee < 8; ee++) {
            int e = e0 + ee;
            float v = sb1[e];
#pragma unroll
            for (int c = 0; c < 8; c++) v = fmaf(y[c], sW1[c * 32 + e], v);
            dst[ee] = gelu_f(v);
        }
    }
    __syncthreads();

    // Phase 2: depthwise 3x3 conv + gelu for 32 interior tokens, 8 thr/token (4ch each)
    int tl = threadIdx.x >> 3, sub = threadIdx.x & 7, e0 = sub * 4;
    int li = tl >> 3, lj = tl & 7;
    {
        float acc[4];
#pragma unroll
        for (int ee = 0; ee < 4; ee++) acc[ee] = sb2[e0 + ee];
#pragma unroll
        for (int di = 0; di < 3; di++) {
#pragma unroll
            for (int dj = 0; dj < 3; dj++) {
                const float* tp = st1 + ((li + di) * 10 + (lj + dj)) * 36 + e0;
                const float* wp = sW2 + (di * 3 + dj) * 32 + e0;
                acc[0] = fmaf(tp[0], wp[0], acc[0]);
                acc[1] = fmaf(tp[1], wp[1], acc[1]);
                acc[2] = fmaf(tp[2], wp[2], acc[2]);
                acc[3] = fmaf(tp[3], wp[3], acc[3]);
            }
        }
        float* o = st2 + tl * 36 + e0;
        o[0] = gelu_f(acc[0]); o[1] = gelu_f(acc[1]);
        o[2] = gelu_f(acc[2]); o[3] = gelu_f(acc[3]);
    }
    __syncthreads();

    // Phase 3: MLP3 (32->8) + residual, 1 out channel per thread
    int c = sub;
    float a = sb3[c] + sx2[tl * 8 + c];
    const float* t2p = st2 + tl * 36;
#pragma unroll
    for (int q4 = 0; q4 < 8; q4++) {
        float4 tv = *(const float4*)(t2p + q4 * 4);
        int e = q4 * 4;
        a = fmaf(tv.x, sW3[(e + 0) * 8 + c], a);
        a = fmaf(tv.y, sW3[(e + 1) * 8 + c], a);
        a = fmaf(tv.z, sW3[(e + 2) * 8 + c], a);
        a = fmaf(tv.w, sW3[(e + 3) * 8 + c], a);
    }
    int p = (b << 12) | ((ti * 4 + li) << 6) | (tj * 8 + lj);
    out[p * 8 + c] = a;
}

extern "C" void kernel_launch(void* const* d_in, const int* in_sizes, int n_in,
                              void* d_out, int out_size) {
    const float* x      = (const float*)d_in[0];
    const float* conv_W = (const float*)d_in[1];
    const float* conv_b = (const float*)d_in[2];
    const float* Wq     = (const float*)d_in[3];
    const float* Wk     = (const float*)d_in[4];
    const float* Wv     = (const float*)d_in[5];
    const float* pos    = (const float*)d_in[6];
    const float* Wo     = (const float*)d_in[7];
    const float* m1W    = (const float*)d_in[8];
    const float* m1b    = (const float*)d_in[9];
    const float* m2W    = (const float*)d_in[10];
    const float* m2b    = (const float*)d_in[11];
    const float* m3W    = (const float*)d_in[12];
    const float* m3b    = (const float*)d_in[13];
    float* out = (float*)d_out;

    const int ATTN_SMEM = (8192 + 128 * PP2) * 4;   // 68608 bytes
    cudaFuncSetAttribute(k_attn, cudaFuncAttributeMaxDynamicSharedMemorySize, ATTN_SMEM);

    k_conv_qkv<<<256, 256>>>(x, conv_W, conv_b, Wq, Wk, Wv);
    dim3 ag(64, 4);
    k_attn<<<ag, 256, ATTN_SMEM>>>(pos);
    k_tail<<<256, 256>>>(Wo, m1W, m1b, m2W, m2b, m3W, m3b, out);
}